// round 1
// baseline (speedup 1.0000x reference)
#include <cuda_runtime.h>
#include <cuda_bf16.h>
#include <cstdint>

// ============================================================================
// Shapes (fixed for this problem)
//   B=8, L=S=1024, G=64, D=1024, H=16, d_head=64
// Inputs (metadata order):
//   0 queries (8,1024,1024)  1 keys  2 values  3 routers (8,64,1024)
//   4 Wq 5 Wk 6 Wv 7 Wlq 8 Wlk 9 Wo (1024,1024)  10 bo (1024)
// Output: (8,1024,1024) fp32
// ============================================================================

#define D_MODEL 1024
#define NB 8
#define NL 1024
#define NG 64
#define NH 16
#define DH 64

// -------------------- scratch (device globals; no allocation) ---------------
__device__ float g_Q [NB * NL * D_MODEL];   // projected queries  (8192,1024)
__device__ float g_K [NB * NL * D_MODEL];   // projected keys
__device__ float g_V [NB * NL * D_MODEL];   // projected values
__device__ float g_RQ[NB * NG * D_MODEL];   // projected router-q (512,1024)
__device__ float g_RK[NB * NG * D_MODEL];   // projected router-k
__device__ float g_WEP[NB * NH * DH * DH];  // per-(b,h) 64x64 bilinear matrix
__device__ float g_OT[NB * NL * D_MODEL];   // attention out, layout [b][h*64+d][l]

// ============================================================================
// Kernel 1: SGEMM  C = A(MxK) @ B(KxN) (+bias), K=N=1024 here.
// 128x128 blocktile, BK=8, 256 threads, 8x8 microtile.
// ============================================================================
#define BM 128
#define BN 128
#define BK 8
#define TM 8
#define TN 8

__global__ __launch_bounds__(256, 2)
void sgemm_kernel(const float* __restrict__ A, const float* __restrict__ B,
                  float* __restrict__ C, const float* __restrict__ bias,
                  int M, int N, int K)
{
    __shared__ float As[BK][BM];
    __shared__ float Bs[BK][BN];

    const int tid  = threadIdx.x;
    const int brow = blockIdx.y;
    const int bcol = blockIdx.x;

    const float* Ab = A + (size_t)brow * BM * K;
    const float* Bb = B + (size_t)bcol * BN;

    const int aRow = tid >> 1;          // 0..127
    const int aCol = (tid & 1) * 4;     // 0 or 4
    const int bRow = tid >> 5;          // 0..7
    const int bCol = (tid & 31) * 4;    // 0..124

    const int tRow = (tid >> 4) * TM;   // 0..120
    const int tCol = (tid & 15) * TN;   // 0..120

    float acc[TM][TN] = {};
    float regM[TM], regN[TN];

    for (int k0 = 0; k0 < K; k0 += BK) {
        float4 a4 = *(const float4*)(Ab + (size_t)aRow * K + k0 + aCol);
        As[aCol + 0][aRow] = a4.x;
        As[aCol + 1][aRow] = a4.y;
        As[aCol + 2][aRow] = a4.z;
        As[aCol + 3][aRow] = a4.w;
        float4 b4 = *(const float4*)(Bb + (size_t)(k0 + bRow) * N + bCol);
        *(float4*)&Bs[bRow][bCol] = b4;
        __syncthreads();

        #pragma unroll
        for (int kk = 0; kk < BK; kk++) {
            #pragma unroll
            for (int i = 0; i < TM; i++) regM[i] = As[kk][tRow + i];
            #pragma unroll
            for (int j = 0; j < TN; j++) regN[j] = Bs[kk][tCol + j];
            #pragma unroll
            for (int i = 0; i < TM; i++)
                #pragma unroll
                for (int j = 0; j < TN; j++)
                    acc[i][j] += regM[i] * regN[j];
        }
        __syncthreads();
    }

    #pragma unroll
    for (int i = 0; i < TM; i++) {
        float* crow = C + (size_t)(brow * BM + tRow + i) * N + bcol * BN + tCol;
        #pragma unroll
        for (int j = 0; j < TN; j += 4) {
            float4 v;
            v.x = acc[i][j + 0]; v.y = acc[i][j + 1];
            v.z = acc[i][j + 2]; v.w = acc[i][j + 3];
            if (bias) {
                const float* bp = bias + bcol * BN + tCol + j;
                v.x += bp[0]; v.y += bp[1]; v.z += bp[2]; v.w += bp[3];
            }
            *(float4*)(crow + j) = v;
        }
    }
}

// ============================================================================
// Kernel 2: W_ep[bh][d][e] = sum_g rq[b,g,h*64+d] * rk[b,g,h*64+e]
// One block per (b,h); 256 threads; 4x4 microtiles on a 16x16 thread grid.
// ============================================================================
#define AP 68   // smem pitch (floats): 16B-aligned rows, conflict-friendly

__global__ __launch_bounds__(256)
void wep_kernel(const float* __restrict__ RQ, const float* __restrict__ RK,
                float* __restrict__ WEP)
{
    __shared__ float sA[64 * AP];   // rq [g][d]
    __shared__ float sB[64 * AP];   // rk [g][e]

    const int tid = threadIdx.x;
    const int bh  = blockIdx.x;
    const int b   = bh >> 4, h = bh & 15;

    const int ldr = tid >> 2;           // row 0..63
    const int lds = (tid & 3) * 16;     // col segment

    const float* rqg = RQ + (size_t)(b * NG) * D_MODEL + h * DH;
    const float* rkg = RK + (size_t)(b * NG) * D_MODEL + h * DH;

    #pragma unroll
    for (int s = 0; s < 4; s++) {
        *(float4*)&sA[ldr * AP + lds + s * 4] =
            *(const float4*)(rqg + (size_t)ldr * D_MODEL + lds + s * 4);
        *(float4*)&sB[ldr * AP + lds + s * 4] =
            *(const float4*)(rkg + (size_t)ldr * D_MODEL + lds + s * 4);
    }
    __syncthreads();

    const int tRow = (tid >> 4) * 4;
    const int tCol = (tid & 15) * 4;
    float acc[4][4] = {};
    #pragma unroll 8
    for (int g = 0; g < 64; g++) {
        float rm[4], rn[4];
        #pragma unroll
        for (int i = 0; i < 4; i++) rm[i] = sA[g * AP + tRow + i];
        #pragma unroll
        for (int j = 0; j < 4; j++) rn[j] = sB[g * AP + tCol + j];
        #pragma unroll
        for (int i = 0; i < 4; i++)
            #pragma unroll
            for (int j = 0; j < 4; j++)
                acc[i][j] += rm[i] * rn[j];
    }

    float* wout = WEP + (size_t)bh * (DH * DH);
    #pragma unroll
    for (int i = 0; i < 4; i++)
        #pragma unroll
        for (int j = 0; j < 4; j++)
            wout[(tRow + i) * DH + tCol + j] = acc[i][j];
}

// ============================================================================
// Kernel 3: fused q' = q @ W_ep, flash attention, transposed output.
// Grid: (16 q-tiles, 128 bh). 256 threads. Dynamic smem: 4 tiles of 64xAP.
// Output: g_OT[b][(h*64+d)][l]  (the reference's reshape-transpose, fused).
// ============================================================================
__global__ __launch_bounds__(256)
void attn_kernel(const float* __restrict__ Qp, const float* __restrict__ Kp,
                 const float* __restrict__ Vp, const float* __restrict__ WEP,
                 float* __restrict__ Ot)
{
    extern __shared__ float smem[];
    float* sQ = smem;              // q' tile, [m][e]
    float* sK = sQ + 64 * AP;      // phase A: q_in [m][dk]; phase B: K^T [e][n]
    float* sV = sK + 64 * AP;      // phase A: wep  [dk][e]; phase B: V [n][d]
    float* sP = sV + 64 * AP;      // P tile [m][n]; final: O^T [d][m]

    const int tid = threadIdx.x;
    const int mt  = blockIdx.x;     // 0..15 (q tile)
    const int bh  = blockIdx.y;     // 0..127
    const int b   = bh >> 4, h = bh & 15;
    const int l0  = mt * 64;

    const int tRow = (tid >> 4) * 4;
    const int tCol = (tid & 15) * 4;
    const int ldr  = tid >> 2;            // loader row 0..63
    const int lds  = (tid & 3) * 16;      // loader col segment

    // ---------------- Phase A: q' = q_tile @ W_ep --------------------------
    {
        const float* qg = Qp + (size_t)(b * NL + l0) * D_MODEL + h * DH;
        const float* wg = WEP + (size_t)bh * (DH * DH);
        #pragma unroll
        for (int s = 0; s < 4; s++) {
            *(float4*)&sK[ldr * AP + lds + s * 4] =
                *(const float4*)(qg + (size_t)ldr * D_MODEL + lds + s * 4);
            *(float4*)&sV[ldr * AP + lds + s * 4] =
                *(const float4*)(wg + ldr * DH + lds + s * 4);
        }
    }
    __syncthreads();
    {
        float acc[4][4] = {};
        #pragma unroll 8
        for (int kk = 0; kk < 64; kk++) {
            float rm[4], rn[4];
            #pragma unroll
            for (int i = 0; i < 4; i++) rm[i] = sK[(tRow + i) * AP + kk];
            #pragma unroll
            for (int j = 0; j < 4; j++) rn[j] = sV[kk * AP + tCol + j];
            #pragma unroll
            for (int i = 0; i < 4; i++)
                #pragma unroll
                for (int j = 0; j < 4; j++)
                    acc[i][j] += rm[i] * rn[j];
        }
        #pragma unroll
        for (int i = 0; i < 4; i++)
            #pragma unroll
            for (int j = 0; j < 4; j++)
                sQ[(tRow + i) * AP + tCol + j] = acc[i][j];
    }

    // ---------------- Phase B: flash attention over S ----------------------
    float mMax[4], lSum[4], o[4][4];
    #pragma unroll
    for (int i = 0; i < 4; i++) {
        mMax[i] = -1e30f; lSum[i] = 0.f;
        #pragma unroll
        for (int j = 0; j < 4; j++) o[i][j] = 0.f;
    }

    const float* kg = Kp + (size_t)b * NL * D_MODEL + h * DH;
    const float* vg = Vp + (size_t)b * NL * D_MODEL + h * DH;
    const float scale = 0.125f;   // 1/sqrt(64)

    for (int s0 = 0; s0 < NL; s0 += 64) {
        __syncthreads();  // sQ writes visible (first iter); sK/sV/sP reuse safe
        // K tile transposed -> sK[e][n]; V tile natural -> sV[n][d]
        #pragma unroll
        for (int s = 0; s < 4; s++) {
            float4 kv = *(const float4*)(kg + (size_t)(s0 + ldr) * D_MODEL + lds + s * 4);
            sK[(lds + s * 4 + 0) * AP + ldr] = kv.x;
            sK[(lds + s * 4 + 1) * AP + ldr] = kv.y;
            sK[(lds + s * 4 + 2) * AP + ldr] = kv.z;
            sK[(lds + s * 4 + 3) * AP + ldr] = kv.w;
            *(float4*)&sV[ldr * AP + lds + s * 4] =
                *(const float4*)(vg + (size_t)(s0 + ldr) * D_MODEL + lds + s * 4);
        }
        __syncthreads();

        // scores tile: S[m][n] = scale * sum_e q'[m][e] K[n][e]
        float sc[4][4] = {};
        #pragma unroll 8
        for (int kk = 0; kk < 64; kk++) {
            float rm[4], rn[4];
            #pragma unroll
            for (int i = 0; i < 4; i++) rm[i] = sQ[(tRow + i) * AP + kk];
            #pragma unroll
            for (int j = 0; j < 4; j++) rn[j] = sK[kk * AP + tCol + j];
            #pragma unroll
            for (int i = 0; i < 4; i++)
                #pragma unroll
                for (int j = 0; j < 4; j++)
                    sc[i][j] += rm[i] * rn[j];
        }

        // online softmax; write P tile
        #pragma unroll
        for (int i = 0; i < 4; i++) {
            float rmax = -1e30f;
            #pragma unroll
            for (int j = 0; j < 4; j++) {
                sc[i][j] *= scale;
                rmax = fmaxf(rmax, sc[i][j]);
            }
            #pragma unroll
            for (int off = 8; off >= 1; off >>= 1)
                rmax = fmaxf(rmax, __shfl_xor_sync(0xffffffffu, rmax, off));
            float newM = fmaxf(mMax[i], rmax);
            float corr = __expf(mMax[i] - newM);
            mMax[i] = newM;
            float psum = 0.f;
            #pragma unroll
            for (int j = 0; j < 4; j++) {
                float p = __expf(sc[i][j] - newM);
                sP[(tRow + i) * AP + tCol + j] = p;
                psum += p;
            }
            #pragma unroll
            for (int off = 8; off >= 1; off >>= 1)
                psum += __shfl_xor_sync(0xffffffffu, psum, off);
            lSum[i] = lSum[i] * corr + psum;
            #pragma unroll
            for (int j = 0; j < 4; j++) o[i][j] *= corr;
        }
        __syncthreads();

        // O += P @ V
        #pragma unroll 8
        for (int kk = 0; kk < 64; kk++) {
            float rm[4], rn[4];
            #pragma unroll
            for (int i = 0; i < 4; i++) rm[i] = sP[(tRow + i) * AP + kk];
            #pragma unroll
            for (int j = 0; j < 4; j++) rn[j] = sV[kk * AP + tCol + j];
            #pragma unroll
            for (int i = 0; i < 4; i++)
                #pragma unroll
                for (int j = 0; j < 4; j++)
                    o[i][j] += rm[i] * rn[j];
        }
    }
    __syncthreads();

    // normalize, transpose through smem, write Ot[b][(h*64+d)][l0+m] coalesced
    #pragma unroll
    for (int i = 0; i < 4; i++) {
        float inv = 1.0f / lSum[i];
        #pragma unroll
        for (int j = 0; j < 4; j++)
            sP[(tCol + j) * AP + tRow + i] = o[i][j] * inv;   // sP[d][m]
    }
    __syncthreads();

    float* og = Ot + (size_t)b * NL * D_MODEL + (size_t)(h * DH) * NL + l0;
    #pragma unroll
    for (int s = 0; s < 4; s++) {
        float4 v = *(const float4*)&sP[ldr * AP + lds + s * 4];
        *(float4*)(og + (size_t)ldr * NL + lds + s * 4) = v;
    }
}

// ============================================================================
// Launch
// ============================================================================
extern "C" void kernel_launch(void* const* d_in, const int* in_sizes, int n_in,
                              void* d_out, int out_size)
{
    const float* queries = (const float*)d_in[0];
    const float* keys    = (const float*)d_in[1];
    const float* values  = (const float*)d_in[2];
    const float* routers = (const float*)d_in[3];
    const float* Wq      = (const float*)d_in[4];
    const float* Wk      = (const float*)d_in[5];
    const float* Wv      = (const float*)d_in[6];
    const float* Wlq     = (const float*)d_in[7];
    const float* Wlk     = (const float*)d_in[8];
    const float* Wo      = (const float*)d_in[9];
    const float* bo      = (const float*)d_in[10];
    float* out           = (float*)d_out;

    float *Qp, *Kp, *Vp, *RQ, *RK, *WEP, *OT;
    cudaGetSymbolAddress((void**)&Qp,  g_Q);
    cudaGetSymbolAddress((void**)&Kp,  g_K);
    cudaGetSymbolAddress((void**)&Vp,  g_V);
    cudaGetSymbolAddress((void**)&RQ,  g_RQ);
    cudaGetSymbolAddress((void**)&RK,  g_RK);
    cudaGetSymbolAddress((void**)&WEP, g_WEP);
    cudaGetSymbolAddress((void**)&OT,  g_OT);

    const int M  = NB * NL;   // 8192
    const int Mr = NB * NG;   // 512
    const int N  = D_MODEL, K = D_MODEL;

    dim3 gBig(N / BN, M / BM);
    dim3 gRtr(N / BN, Mr / BM);

    // projections
    sgemm_kernel<<<gBig, 256>>>(queries, Wq, Qp, nullptr, M,  N, K);
    sgemm_kernel<<<gBig, 256>>>(keys,    Wk, Kp, nullptr, M,  N, K);
    sgemm_kernel<<<gBig, 256>>>(values,  Wv, Vp, nullptr, M,  N, K);
    sgemm_kernel<<<gRtr, 256>>>(routers, Wlq, RQ, nullptr, Mr, N, K);
    sgemm_kernel<<<gRtr, 256>>>(routers, Wlk, RK, nullptr, Mr, N, K);

    // per-head bilinear matrices
    wep_kernel<<<NB * NH, 256>>>(RQ, RK, WEP);

    // fused q@Wep + flash attention (+ transposed store)
    const int smemBytes = 4 * 64 * AP * (int)sizeof(float);   // 69,632 B
    cudaFuncSetAttribute(attn_kernel,
                         cudaFuncAttributeMaxDynamicSharedMemorySize, smemBytes);
    dim3 gAtt(NL / 64, NB * NH);   // (16, 128)
    attn_kernel<<<gAtt, 256, smemBytes>>>(Qp, Kp, Vp, WEP, OT);

    // final GEMM with bias: out[b, r, :] = OT[b, r, :] @ Wo + bo
    sgemm_kernel<<<gBig, 256>>>(OT, Wo, out, bo, M, N, K);
}

// round 3
// speedup vs baseline: 1.9189x; 1.9189x over previous
#include <cuda_runtime.h>
#include <cuda_bf16.h>
#include <cstdint>

// ============================================================================
// Shapes (fixed): B=8, L=S=1024, G=64, D=1024, H=16, d_head=64
// Inputs: 0 queries 1 keys 2 values 3 routers 4 Wq 5 Wk 6 Wv 7 Wlq 8 Wlk 9 Wo 10 bo
// Output: (8,1024,1024) fp32
// NOTE: harness compiles PTX at compute_103 (no 'a') -> tcgen05 unavailable.
// Use warp-level mma.sync (bf16, split hi/lo precision) for all big GEMMs.
// ============================================================================

#define D_MODEL 1024
#define NB 8
#define NL 1024
#define NG 64
#define NH 16
#define DH 64

// -------------------- scratch (device globals; no allocation) ---------------
__device__ float g_Q [NB * NL * D_MODEL];
__device__ float g_K [NB * NL * D_MODEL];
__device__ float g_V [NB * NL * D_MODEL];
__device__ float g_RQ[NB * NG * D_MODEL];
__device__ float g_RK[NB * NG * D_MODEL];
__device__ float g_WEP[NB * NH * DH * DH];
__device__ float g_OT[NB * NL * D_MODEL];           // attention out [b][h*64+d][l]
__device__ __nv_bfloat16 g_Ahi[NB * NL * D_MODEL];
__device__ __nv_bfloat16 g_Alo[NB * NL * D_MODEL];
__device__ __nv_bfloat16 g_Whi[D_MODEL * D_MODEL];  // transposed weight hi [n][k]
__device__ __nv_bfloat16 g_Wlo[D_MODEL * D_MODEL];  // transposed weight lo [n][k]

// ============================================================================
// PTX helpers (all plain sm_80+-era instructions; safe at compute_103)
// ============================================================================
__device__ __forceinline__ uint32_t smem_u32(const void* p) {
    uint32_t a;
    asm("{ .reg .u64 t; cvta.to.shared.u64 t, %1; cvt.u32.u64 %0, t; }" : "=r"(a) : "l"(p));
    return a;
}
#define CP_ASYNC16(dst, src) \
    asm volatile("cp.async.cg.shared.global [%0], [%1], 16;" :: "r"(dst), "l"(src))
#define CP_COMMIT() asm volatile("cp.async.commit_group;" ::: "memory")

__device__ __forceinline__ void ldmx4(uint32_t* r, uint32_t addr) {
    asm volatile("ldmatrix.sync.aligned.m8n8.x4.shared.b16 {%0,%1,%2,%3}, [%4];"
                 : "=r"(r[0]), "=r"(r[1]), "=r"(r[2]), "=r"(r[3]) : "r"(addr));
}
__device__ __forceinline__ void mma_bf16(float* c, const uint32_t* a, const uint32_t* b) {
    asm volatile(
        "mma.sync.aligned.m16n8k16.row.col.f32.bf16.bf16.f32 "
        "{%0,%1,%2,%3}, {%4,%5,%6,%7}, {%8,%9}, {%0,%1,%2,%3};"
        : "+f"(c[0]), "+f"(c[1]), "+f"(c[2]), "+f"(c[3])
        : "r"(a[0]), "r"(a[1]), "r"(a[2]), "r"(a[3]), "r"(b[0]), "r"(b[1]));
}

// ============================================================================
// Conversion kernels
// ============================================================================
__global__ __launch_bounds__(256)
void conv_hilo_kernel(const float* __restrict__ in, __nv_bfloat16* __restrict__ hi,
                      __nv_bfloat16* __restrict__ lo, int n)
{
    int i = (blockIdx.x * 256 + threadIdx.x) * 4;
    if (i >= n) return;
    float4 v = *(const float4*)(in + i);
    __nv_bfloat16 h0 = __float2bfloat16_rn(v.x);
    __nv_bfloat16 h1 = __float2bfloat16_rn(v.y);
    __nv_bfloat16 h2 = __float2bfloat16_rn(v.z);
    __nv_bfloat16 h3 = __float2bfloat16_rn(v.w);
    __nv_bfloat162 hp0; hp0.x = h0; hp0.y = h1;
    __nv_bfloat162 hp1; hp1.x = h2; hp1.y = h3;
    *(__nv_bfloat162*)(hi + i)     = hp0;
    *(__nv_bfloat162*)(hi + i + 2) = hp1;
    __nv_bfloat162 lp0, lp1;
    lp0.x = __float2bfloat16_rn(v.x - __bfloat162float(h0));
    lp0.y = __float2bfloat16_rn(v.y - __bfloat162float(h1));
    lp1.x = __float2bfloat16_rn(v.z - __bfloat162float(h2));
    lp1.y = __float2bfloat16_rn(v.w - __bfloat162float(h3));
    *(__nv_bfloat162*)(lo + i)     = lp0;
    *(__nv_bfloat162*)(lo + i + 2) = lp1;
}

// W[k][n] (1024x1024) -> Wt_hi/lo[n][k]
__global__ __launch_bounds__(256)
void conv_wt_kernel(const float* __restrict__ W, __nv_bfloat16* __restrict__ th,
                    __nv_bfloat16* __restrict__ tl)
{
    __shared__ float t[32][33];
    int bn = blockIdx.x * 32, bk = blockIdx.y * 32;
    int tx = threadIdx.x & 31, ty = threadIdx.x >> 5;   // 32x8
    #pragma unroll
    for (int j = 0; j < 32; j += 8)
        t[ty + j][tx] = W[(size_t)(bk + ty + j) * D_MODEL + bn + tx];
    __syncthreads();
    #pragma unroll
    for (int j = 0; j < 32; j += 8) {
        float v = t[tx][ty + j];
        __nv_bfloat16 h = __float2bfloat16_rn(v);
        size_t o = (size_t)(bn + ty + j) * D_MODEL + bk + tx;
        th[o] = h;
        tl[o] = __float2bfloat16_rn(v - __bfloat162float(h));
    }
}

// ============================================================================
// mma.sync split-bf16 GEMM: C[M,N] = A[M,K] @ W[K,N] (+bias)
// A as Ahi/Alo [M][K]; W transposed as Bhi/Blo [N][K].
// 128x128 block tile, BK=64, 8 warps (4 m x 2 n), warp tile 32x64.
// Double-buffered cp.async stages with XOR-16B swizzle; ldmatrix fragments.
// ============================================================================
#define ARR_BYTES   16384                 // one operand tile: 128 rows x 128B
#define STAGE_BYTES (4 * ARR_BYTES)       // Ahi,Alo,Bhi,Blo
#define GEMM_SMEM   (2 * STAGE_BYTES)     // 131072

__global__ __launch_bounds__(256, 1)
void gemm_mma_kernel(const __nv_bfloat16* __restrict__ Ahi,
                     const __nv_bfloat16* __restrict__ Alo,
                     const __nv_bfloat16* __restrict__ Bhi,
                     const __nv_bfloat16* __restrict__ Blo,
                     float* __restrict__ C, const float* __restrict__ bias,
                     int M, int N, int K)
{
    extern __shared__ char smem[];
    const uint32_t sbase = smem_u32(smem);
    const int tid  = threadIdx.x;
    const int wid  = tid >> 5, lane = tid & 31;
    const int wm   = wid & 3;         // m warp: rows wm*32..+31
    const int wn   = wid >> 2;        // n warp: cols wn*64..+63
    const int m0   = blockIdx.y * 128;
    const int n0   = blockIdx.x * 128;
    const int nchunks = K >> 6;       // K/64

    const __nv_bfloat16* srcs[4] = { Ahi + (size_t)m0 * K, Alo + (size_t)m0 * K,
                                     Bhi + (size_t)n0 * K, Blo + (size_t)n0 * K };

    // ---- async stage loader: 4 arrays x 1024 16B units ----
    auto issue = [&](int c, int s) {
        const uint32_t stb = sbase + s * STAGE_BYTES;
        #pragma unroll
        for (int a = 0; a < 4; a++) {
            const __nv_bfloat16* src = srcs[a] + c * 64;
            const uint32_t ab = stb + a * ARR_BYTES;
            #pragma unroll
            for (int i = 0; i < 4; i++) {
                int u   = tid + i * 256;
                int row = u >> 3, c8 = u & 7;
                uint32_t dst = ab + row * 128 + ((c8 ^ (row & 7)) << 4);
                CP_ASYNC16(dst, src + (size_t)row * K + c8 * 8);
            }
        }
        CP_COMMIT();
    };

    issue(0, 0);

    float acc[2][8][4] = {};

    // per-lane fragment address components
    const int a_row0 = wm * 32 + (lane & 15);
    const int a_sub  = lane >> 4;               // k-subtile (0/+8 elems)
    const int g      = lane >> 3;
    const int b_noff = ((g & 2) << 2) + (lane & 7);
    const int b_sub  = g & 1;

    for (int c = 0; c < nchunks; c++) {
        const int s = c & 1;
        if (c + 1 < nchunks) {
            issue(c + 1, s ^ 1);
            asm volatile("cp.async.wait_group 1;" ::: "memory");
        } else {
            asm volatile("cp.async.wait_group 0;" ::: "memory");
        }
        __syncthreads();

        const uint32_t stb = sbase + s * STAGE_BYTES;
        const uint32_t Ah = stb, Al = stb + ARR_BYTES;
        const uint32_t Bh = stb + 2 * ARR_BYTES, Bl = stb + 3 * ARR_BYTES;

        #pragma unroll
        for (int k16 = 0; k16 < 4; k16++) {
            const int kc = k16 * 2;
            uint32_t ah[2][4], al[2][4], bh[4][4], bl[4][4];
            #pragma unroll
            for (int mi = 0; mi < 2; mi++) {
                int row = a_row0 + mi * 16;
                uint32_t off = row * 128 + (((kc + a_sub) ^ (row & 7)) << 4);
                ldmx4(ah[mi], Ah + off);
                ldmx4(al[mi], Al + off);
            }
            #pragma unroll
            for (int pn = 0; pn < 4; pn++) {
                int n = wn * 64 + pn * 16 + b_noff;
                uint32_t off = n * 128 + (((kc + b_sub) ^ (n & 7)) << 4);
                ldmx4(bh[pn], Bh + off);
                ldmx4(bl[pn], Bl + off);
            }
            #pragma unroll
            for (int mi = 0; mi < 2; mi++)
                #pragma unroll
                for (int ni = 0; ni < 8; ni++) {
                    const uint32_t* bf = &bh[ni >> 1][(ni & 1) * 2];
                    const uint32_t* lf = &bl[ni >> 1][(ni & 1) * 2];
                    mma_bf16(acc[mi][ni], ah[mi], bf);   // hi*hi
                    mma_bf16(acc[mi][ni], al[mi], bf);   // lo*hi
                    mma_bf16(acc[mi][ni], ah[mi], lf);   // hi*lo
                }
        }
        __syncthreads();
    }

    // ---- epilogue: registers -> global fp32 (+bias) ----
    const int tr = lane >> 2, tc = (lane & 3) * 2;
    const int rbase = m0 + wm * 32;
    const int cbase = n0 + wn * 64;
    #pragma unroll
    for (int mi = 0; mi < 2; mi++) {
        #pragma unroll
        for (int ni = 0; ni < 8; ni++) {
            int col = cbase + ni * 8 + tc;
            float bx = 0.f, by = 0.f;
            if (bias) { float2 bv = *(const float2*)(bias + col); bx = bv.x; by = bv.y; }
            int r0 = rbase + mi * 16 + tr;
            float2 v0; v0.x = acc[mi][ni][0] + bx; v0.y = acc[mi][ni][1] + by;
            *(float2*)(C + (size_t)r0 * N + col) = v0;
            float2 v1; v1.x = acc[mi][ni][2] + bx; v1.y = acc[mi][ni][3] + by;
            *(float2*)(C + (size_t)(r0 + 8) * N + col) = v1;
        }
    }
}

// ============================================================================
// W_ep[bh][d][e] = sum_g rq[b,g,h*64+d] * rk[b,g,h*64+e]
// ============================================================================
#define AP 68

__global__ __launch_bounds__(256)
void wep_kernel(const float* __restrict__ RQ, const float* __restrict__ RK,
                float* __restrict__ WEP)
{
    __shared__ float sA[64 * AP];
    __shared__ float sB[64 * AP];
    const int tid = threadIdx.x;
    const int bh  = blockIdx.x;
    const int b   = bh >> 4, h = bh & 15;
    const int ldr = tid >> 2;
    const int lds = (tid & 3) * 16;
    const float* rqg = RQ + (size_t)(b * NG) * D_MODEL + h * DH;
    const float* rkg = RK + (size_t)(b * NG) * D_MODEL + h * DH;
    #pragma unroll
    for (int s = 0; s < 4; s++) {
        *(float4*)&sA[ldr * AP + lds + s * 4] =
            *(const float4*)(rqg + (size_t)ldr * D_MODEL + lds + s * 4);
        *(float4*)&sB[ldr * AP + lds + s * 4] =
            *(const float4*)(rkg + (size_t)ldr * D_MODEL + lds + s * 4);
    }
    __syncthreads();
    const int tRow = (tid >> 4) * 4;
    const int tCol = (tid & 15) * 4;
    float acc[4][4] = {};
    #pragma unroll 8
    for (int g = 0; g < 64; g++) {
        float rm[4], rn[4];
        #pragma unroll
        for (int i = 0; i < 4; i++) rm[i] = sA[g * AP + tRow + i];
        #pragma unroll
        for (int j = 0; j < 4; j++) rn[j] = sB[g * AP + tCol + j];
        #pragma unroll
        for (int i = 0; i < 4; i++)
            #pragma unroll
            for (int j = 0; j < 4; j++)
                acc[i][j] += rm[i] * rn[j];
    }
    float* wout = WEP + (size_t)bh * (DH * DH);
    #pragma unroll
    for (int i = 0; i < 4; i++)
        #pragma unroll
        for (int j = 0; j < 4; j++)
            wout[(tRow + i) * DH + tCol + j] = acc[i][j];
}

// ============================================================================
// Fused q' = q @ W_ep + flash attention + transposed store (fp32 CUDA-core)
// ============================================================================
__global__ __launch_bounds__(256)
void attn_kernel(const float* __restrict__ Qp, const float* __restrict__ Kp,
                 const float* __restrict__ Vp, const float* __restrict__ WEP,
                 float* __restrict__ Ot)
{
    extern __shared__ float fsm[];
    float* sQ = fsm;
    float* sK = sQ + 64 * AP;
    float* sV = sK + 64 * AP;
    float* sP = sV + 64 * AP;

    const int tid = threadIdx.x;
    const int mt  = blockIdx.x;
    const int bh  = blockIdx.y;
    const int b   = bh >> 4, h = bh & 15;
    const int l0  = mt * 64;
    const int tRow = (tid >> 4) * 4;
    const int tCol = (tid & 15) * 4;
    const int ldr  = tid >> 2;
    const int lds  = (tid & 3) * 16;

    {
        const float* qg = Qp + (size_t)(b * NL + l0) * D_MODEL + h * DH;
        const float* wg = WEP + (size_t)bh * (DH * DH);
        #pragma unroll
        for (int s = 0; s < 4; s++) {
            *(float4*)&sK[ldr * AP + lds + s * 4] =
                *(const float4*)(qg + (size_t)ldr * D_MODEL + lds + s * 4);
            *(float4*)&sV[ldr * AP + lds + s * 4] =
                *(const float4*)(wg + ldr * DH + lds + s * 4);
        }
    }
    __syncthreads();
    {
        float acc[4][4] = {};
        #pragma unroll 8
        for (int kk = 0; kk < 64; kk++) {
            float rm[4], rn[4];
            #pragma unroll
            for (int i = 0; i < 4; i++) rm[i] = sK[(tRow + i) * AP + kk];
            #pragma unroll
            for (int j = 0; j < 4; j++) rn[j] = sV[kk * AP + tCol + j];
            #pragma unroll
            for (int i = 0; i < 4; i++)
                #pragma unroll
                for (int j = 0; j < 4; j++)
                    acc[i][j] += rm[i] * rn[j];
        }
        #pragma unroll
        for (int i = 0; i < 4; i++)
            #pragma unroll
            for (int j = 0; j < 4; j++)
                sQ[(tRow + i) * AP + tCol + j] = acc[i][j];
    }

    float mMax[4], lSum[4], o[4][4];
    #pragma unroll
    for (int i = 0; i < 4; i++) {
        mMax[i] = -1e30f; lSum[i] = 0.f;
        #pragma unroll
        for (int j = 0; j < 4; j++) o[i][j] = 0.f;
    }

    const float* kg = Kp + (size_t)b * NL * D_MODEL + h * DH;
    const float* vg = Vp + (size_t)b * NL * D_MODEL + h * DH;
    const float scale = 0.125f;

    for (int s0 = 0; s0 < NL; s0 += 64) {
        __syncthreads();
        #pragma unroll
        for (int s = 0; s < 4; s++) {
            float4 kv = *(const float4*)(kg + (size_t)(s0 + ldr) * D_MODEL + lds + s * 4);
            sK[(lds + s * 4 + 0) * AP + ldr] = kv.x;
            sK[(lds + s * 4 + 1) * AP + ldr] = kv.y;
            sK[(lds + s * 4 + 2) * AP + ldr] = kv.z;
            sK[(lds + s * 4 + 3) * AP + ldr] = kv.w;
            *(float4*)&sV[ldr * AP + lds + s * 4] =
                *(const float4*)(vg + (size_t)(s0 + ldr) * D_MODEL + lds + s * 4);
        }
        __syncthreads();

        float sc[4][4] = {};
        #pragma unroll 8
        for (int kk = 0; kk < 64; kk++) {
            float rm[4], rn[4];
            #pragma unroll
            for (int i = 0; i < 4; i++) rm[i] = sQ[(tRow + i) * AP + kk];
            #pragma unroll
            for (int j = 0; j < 4; j++) rn[j] = sK[kk * AP + tCol + j];
            #pragma unroll
            for (int i = 0; i < 4; i++)
                #pragma unroll
                for (int j = 0; j < 4; j++)
                    sc[i][j] += rm[i] * rn[j];
        }

        #pragma unroll
        for (int i = 0; i < 4; i++) {
            float rmax = -1e30f;
            #pragma unroll
            for (int j = 0; j < 4; j++) {
                sc[i][j] *= scale;
                rmax = fmaxf(rmax, sc[i][j]);
            }
            #pragma unroll
            for (int off = 8; off >= 1; off >>= 1)
                rmax = fmaxf(rmax, __shfl_xor_sync(0xffffffffu, rmax, off));
            float newM = fmaxf(mMax[i], rmax);
            float corr = __expf(mMax[i] - newM);
            mMax[i] = newM;
            float psum = 0.f;
            #pragma unroll
            for (int j = 0; j < 4; j++) {
                float p = __expf(sc[i][j] - newM);
                sP[(tRow + i) * AP + tCol + j] = p;
                psum += p;
            }
            #pragma unroll
            for (int off = 8; off >= 1; off >>= 1)
                psum += __shfl_xor_sync(0xffffffffu, psum, off);
            lSum[i] = lSum[i] * corr + psum;
            #pragma unroll
            for (int j = 0; j < 4; j++) o[i][j] *= corr;
        }
        __syncthreads();

        #pragma unroll 8
        for (int kk = 0; kk < 64; kk++) {
            float rm[4], rn[4];
            #pragma unroll
            for (int i = 0; i < 4; i++) rm[i] = sP[(tRow + i) * AP + kk];
            #pragma unroll
            for (int j = 0; j < 4; j++) rn[j] = sV[kk * AP + tCol + j];
            #pragma unroll
            for (int i = 0; i < 4; i++)
                #pragma unroll
                for (int j = 0; j < 4; j++)
                    o[i][j] += rm[i] * rn[j];
        }
    }
    __syncthreads();

    #pragma unroll
    for (int i = 0; i < 4; i++) {
        float inv = 1.0f / lSum[i];
        #pragma unroll
        for (int j = 0; j < 4; j++)
            sP[(tCol + j) * AP + tRow + i] = o[i][j] * inv;
    }
    __syncthreads();

    float* og = Ot + (size_t)b * NL * D_MODEL + (size_t)(h * DH) * NL + l0;
    #pragma unroll
    for (int s = 0; s < 4; s++) {
        float4 v = *(const float4*)&sP[ldr * AP + lds + s * 4];
        *(float4*)(og + (size_t)ldr * NL + lds + s * 4) = v;
    }
}

// ============================================================================
// Launch
// ============================================================================
extern "C" void kernel_launch(void* const* d_in, const int* in_sizes, int n_in,
                              void* d_out, int out_size)
{
    const float* queries = (const float*)d_in[0];
    const float* keys    = (const float*)d_in[1];
    const float* values  = (const float*)d_in[2];
    const float* routers = (const float*)d_in[3];
    const float* Wq      = (const float*)d_in[4];
    const float* Wk      = (const float*)d_in[5];
    const float* Wv      = (const float*)d_in[6];
    const float* Wlq     = (const float*)d_in[7];
    const float* Wlk     = (const float*)d_in[8];
    const float* Wo      = (const float*)d_in[9];
    const float* bo      = (const float*)d_in[10];
    float* out           = (float*)d_out;

    float *Qp, *Kp, *Vp, *RQ, *RK, *WEP, *OT;
    __nv_bfloat16 *Ahi, *Alo, *Whi, *Wlo;
    cudaGetSymbolAddress((void**)&Qp,  g_Q);
    cudaGetSymbolAddress((void**)&Kp,  g_K);
    cudaGetSymbolAddress((void**)&Vp,  g_V);
    cudaGetSymbolAddress((void**)&RQ,  g_RQ);
    cudaGetSymbolAddress((void**)&RK,  g_RK);
    cudaGetSymbolAddress((void**)&WEP, g_WEP);
    cudaGetSymbolAddress((void**)&OT,  g_OT);
    cudaGetSymbolAddress((void**)&Ahi, g_Ahi);
    cudaGetSymbolAddress((void**)&Alo, g_Alo);
    cudaGetSymbolAddress((void**)&Whi, g_Whi);
    cudaGetSymbolAddress((void**)&Wlo, g_Wlo);

    const int M  = NB * NL;   // 8192
    const int Mr = NB * NG;   // 512
    const int N  = D_MODEL, K = D_MODEL;

    cudaFuncSetAttribute(gemm_mma_kernel,
                         cudaFuncAttributeMaxDynamicSharedMemorySize, GEMM_SMEM);
    cudaFuncSetAttribute(attn_kernel,
                         cudaFuncAttributeMaxDynamicSharedMemorySize,
                         4 * 64 * AP * (int)sizeof(float));

    dim3 cw(32, 32);
    dim3 gBig(N / 128, M / 128);   // (8, 64)
    dim3 gRtr(N / 128, Mr / 128);  // (8, 4)
    const int nBig = M * K, nRtr = Mr * K;

    // Q projection
    conv_hilo_kernel<<<nBig / 1024, 256>>>(queries, Ahi, Alo, nBig);
    conv_wt_kernel<<<cw, 256>>>(Wq, Whi, Wlo);
    gemm_mma_kernel<<<gBig, 256, GEMM_SMEM>>>(Ahi, Alo, Whi, Wlo, Qp, nullptr, M, N, K);
    // K projection
    conv_hilo_kernel<<<nBig / 1024, 256>>>(keys, Ahi, Alo, nBig);
    conv_wt_kernel<<<cw, 256>>>(Wk, Whi, Wlo);
    gemm_mma_kernel<<<gBig, 256, GEMM_SMEM>>>(Ahi, Alo, Whi, Wlo, Kp, nullptr, M, N, K);
    // V projection
    conv_hilo_kernel<<<nBig / 1024, 256>>>(values, Ahi, Alo, nBig);
    conv_wt_kernel<<<cw, 256>>>(Wv, Whi, Wlo);
    gemm_mma_kernel<<<gBig, 256, GEMM_SMEM>>>(Ahi, Alo, Whi, Wlo, Vp, nullptr, M, N, K);
    // router projections (shared activation conversion)
    conv_hilo_kernel<<<nRtr / 1024, 256>>>(routers, Ahi, Alo, nRtr);
    conv_wt_kernel<<<cw, 256>>>(Wlq, Whi, Wlo);
    gemm_mma_kernel<<<gRtr, 256, GEMM_SMEM>>>(Ahi, Alo, Whi, Wlo, RQ, nullptr, Mr, N, K);
    conv_wt_kernel<<<cw, 256>>>(Wlk, Whi, Wlo);
    gemm_mma_kernel<<<gRtr, 256, GEMM_SMEM>>>(Ahi, Alo, Whi, Wlo, RK, nullptr, Mr, N, K);

    // per-head bilinear matrices
    wep_kernel<<<NB * NH, 256>>>(RQ, RK, WEP);

    // fused q@Wep + flash attention (+ transposed store)
    dim3 gAtt(NL / 64, NB * NH);
    attn_kernel<<<gAtt, 256, 4 * 64 * AP * (int)sizeof(float)>>>(Qp, Kp, Vp, WEP, OT);

    // final GEMM with bias
    conv_hilo_kernel<<<nBig / 1024, 256>>>(OT, Ahi, Alo, nBig);
    conv_wt_kernel<<<cw, 256>>>(Wo, Whi, Wlo);
    gemm_mma_kernel<<<gBig, 256, GEMM_SMEM>>>(Ahi, Alo, Whi, Wlo, out, bo, M, N, K);
}

// round 5
// speedup vs baseline: 3.0832x; 1.6068x over previous
#include <cuda_runtime.h>
#include <cuda_bf16.h>
#include <cstdint>

// ============================================================================
// Shapes (fixed): B=8, L=S=1024, G=64, D=1024, H=16, d_head=64
// compute_103 PTX: no tcgen05; use mma.sync (HMMA) bf16 with hi/lo split.
// ============================================================================

#define D_MODEL 1024
#define NB 8
#define NL 1024
#define NG 64
#define NH 16
#define DH 64

typedef __nv_bfloat16 bf16;

// -------------------- scratch (device globals; no allocation) ---------------
__device__ float g_K  [NB * NL * D_MODEL];           // projected K fp32
__device__ float g_RQ [NB * NG * D_MODEL];
__device__ float g_RK [NB * NG * D_MODEL];
__device__ float g_WEP[NB * NH * DH * DH];           // per-(b,h) 64x64 (x 1/8)
__device__ bf16 g_Qhi[NB * NL * D_MODEL];            // projected Q hi/lo
__device__ bf16 g_Qlo[NB * NL * D_MODEL];
__device__ bf16 g_Vhi[NB * NL * D_MODEL];            // projected V hi/lo
__device__ bf16 g_Vlo[NB * NL * D_MODEL];
__device__ bf16 g_KPhi[NB * NH * NL * DH];           // K' = K @ Wep^T  [bh][s][64]
__device__ bf16 g_KPlo[NB * NH * NL * DH];
__device__ bf16 g_OThi[NB * NL * D_MODEL];           // attn out^T [b][h*64+d][l]
__device__ bf16 g_OTlo[NB * NL * D_MODEL];
__device__ bf16 g_Ahi[NB * NL * D_MODEL];            // GEMM input planes
__device__ bf16 g_Alo[NB * NL * D_MODEL];
__device__ bf16 g_Whi[D_MODEL * D_MODEL];            // weight^T planes [n][k]
__device__ bf16 g_Wlo[D_MODEL * D_MODEL];

// ============================================================================
// PTX helpers (sm_80-era, safe at compute_103)
// ============================================================================
__device__ __forceinline__ uint32_t smem_u32(const void* p) {
    uint32_t a;
    asm("{ .reg .u64 t; cvta.to.shared.u64 t, %1; cvt.u32.u64 %0, t; }" : "=r"(a) : "l"(p));
    return a;
}
#define CP_ASYNC16(dst, src) \
    asm volatile("cp.async.cg.shared.global [%0], [%1], 16;" :: "r"(dst), "l"(src))
#define CP_COMMIT() asm volatile("cp.async.commit_group;" ::: "memory")
#define CP_WAIT(n)  asm volatile("cp.async.wait_group %0;" :: "n"(n) : "memory")

__device__ __forceinline__ void ldmx4(uint32_t* r, uint32_t addr) {
    asm volatile("ldmatrix.sync.aligned.m8n8.x4.shared.b16 {%0,%1,%2,%3}, [%4];"
                 : "=r"(r[0]), "=r"(r[1]), "=r"(r[2]), "=r"(r[3]) : "r"(addr));
}
__device__ __forceinline__ void ldmx4t(uint32_t* r, uint32_t addr) {
    asm volatile("ldmatrix.sync.aligned.m8n8.x4.trans.shared.b16 {%0,%1,%2,%3}, [%4];"
                 : "=r"(r[0]), "=r"(r[1]), "=r"(r[2]), "=r"(r[3]) : "r"(addr));
}
__device__ __forceinline__ void mma_bf16(float* c, const uint32_t* a, const uint32_t* b) {
    asm volatile(
        "mma.sync.aligned.m16n8k16.row.col.f32.bf16.bf16.f32 "
        "{%0,%1,%2,%3}, {%4,%5,%6,%7}, {%8,%9}, {%0,%1,%2,%3};"
        : "+f"(c[0]), "+f"(c[1]), "+f"(c[2]), "+f"(c[3])
        : "r"(a[0]), "r"(a[1]), "r"(a[2]), "r"(a[3]), "r"(b[0]), "r"(b[1]));
}
__device__ __forceinline__ uint32_t pack_bf16(float lo, float hi) {
    __nv_bfloat162 p = __floats2bfloat162_rn(lo, hi);
    return *(uint32_t*)&p;
}
__device__ __forceinline__ void split_pack(float x, float y, uint32_t& hi, uint32_t& lo) {
    bf16 hx = __float2bfloat16_rn(x), hy = __float2bfloat16_rn(y);
    hi = pack_bf16(__bfloat162float(hx), __bfloat162float(hy));
    __nv_bfloat162 hp; *(uint32_t*)&hp = hi;
    lo = pack_bf16(x - __bfloat162float(hp.x), y - __bfloat162float(hp.y));
}

// ============================================================================
// Conversion kernels
// ============================================================================
__global__ __launch_bounds__(256)
void conv_hilo_kernel(const float* __restrict__ in, bf16* __restrict__ hi,
                      bf16* __restrict__ lo, int n)
{
    int i = (blockIdx.x * 256 + threadIdx.x) * 4;
    if (i >= n) return;
    float4 v = *(const float4*)(in + i);
    uint32_t h0, l0, h1, l1;
    split_pack(v.x, v.y, h0, l0);
    split_pack(v.z, v.w, h1, l1);
    *(uint32_t*)(hi + i) = h0; *(uint32_t*)(hi + i + 2) = h1;
    *(uint32_t*)(lo + i) = l0; *(uint32_t*)(lo + i + 2) = l1;
}

__global__ __launch_bounds__(256)
void conv_wt_kernel(const float* __restrict__ W, bf16* __restrict__ th,
                    bf16* __restrict__ tl)
{
    __shared__ float t[32][33];
    int bn = blockIdx.x * 32, bk = blockIdx.y * 32;
    int tx = threadIdx.x & 31, ty = threadIdx.x >> 5;
    #pragma unroll
    for (int j = 0; j < 32; j += 8)
        t[ty + j][tx] = W[(size_t)(bk + ty + j) * D_MODEL + bn + tx];
    __syncthreads();
    #pragma unroll
    for (int j = 0; j < 32; j += 8) {
        float v = t[tx][ty + j];
        bf16 h = __float2bfloat16_rn(v);
        size_t o = (size_t)(bn + ty + j) * D_MODEL + bk + tx;
        th[o] = h;
        tl[o] = __float2bfloat16_rn(v - __bfloat162float(h));
    }
}

// ============================================================================
// mma.sync split-bf16 GEMM; output fp32 (+bias) or hi/lo bf16 planes.
// ============================================================================
#define ARR_BYTES   16384
#define STAGE_BYTES (4 * ARR_BYTES)
#define GEMM_SMEM   (2 * STAGE_BYTES)

__global__ __launch_bounds__(256, 1)
void gemm_mma_kernel(const bf16* __restrict__ Ahi, const bf16* __restrict__ Alo,
                     const bf16* __restrict__ Bhi, const bf16* __restrict__ Blo,
                     float* __restrict__ Cf, const float* __restrict__ bias,
                     bf16* __restrict__ Chi, bf16* __restrict__ Clo,
                     int M, int N, int K)
{
    extern __shared__ char smem[];
    const uint32_t sbase = smem_u32(smem);
    const int tid  = threadIdx.x;
    const int wid  = tid >> 5, lane = tid & 31;
    const int wm   = wid & 3;
    const int wn   = wid >> 2;
    const int m0   = blockIdx.y * 128;
    const int n0   = blockIdx.x * 128;
    const int nchunks = K >> 6;

    const bf16* srcs[4] = { Ahi + (size_t)m0 * K, Alo + (size_t)m0 * K,
                            Bhi + (size_t)n0 * K, Blo + (size_t)n0 * K };

    auto issue = [&](int c, int s) {
        const uint32_t stb = sbase + s * STAGE_BYTES;
        #pragma unroll
        for (int a = 0; a < 4; a++) {
            const bf16* src = srcs[a] + c * 64;
            const uint32_t ab = stb + a * ARR_BYTES;
            #pragma unroll
            for (int i = 0; i < 4; i++) {
                int u   = tid + i * 256;
                int row = u >> 3, c8 = u & 7;
                uint32_t dst = ab + row * 128 + ((c8 ^ (row & 7)) << 4);
                CP_ASYNC16(dst, src + (size_t)row * K + c8 * 8);
            }
        }
        CP_COMMIT();
    };

    issue(0, 0);

    float acc[2][8][4] = {};
    const int a_row0 = wm * 32 + (lane & 15);
    const int a_sub  = lane >> 4;
    const int g      = lane >> 3;
    const int b_noff = ((g & 2) << 2) + (lane & 7);
    const int b_sub  = g & 1;

    for (int c = 0; c < nchunks; c++) {
        const int s = c & 1;
        if (c + 1 < nchunks) { issue(c + 1, s ^ 1); CP_WAIT(1); }
        else                 { CP_WAIT(0); }
        __syncthreads();

        const uint32_t stb = sbase + s * STAGE_BYTES;
        const uint32_t Ah = stb, Al = stb + ARR_BYTES;
        const uint32_t Bh = stb + 2 * ARR_BYTES, Bl = stb + 3 * ARR_BYTES;

        #pragma unroll
        for (int k16 = 0; k16 < 4; k16++) {
            const int kc = k16 * 2;
            uint32_t ah[2][4], al[2][4], bh[4][4], bl[4][4];
            #pragma unroll
            for (int mi = 0; mi < 2; mi++) {
                int row = a_row0 + mi * 16;
                uint32_t off = row * 128 + (((kc + a_sub) ^ (row & 7)) << 4);
                ldmx4(ah[mi], Ah + off);
                ldmx4(al[mi], Al + off);
            }
            #pragma unroll
            for (int pn = 0; pn < 4; pn++) {
                int n = wn * 64 + pn * 16 + b_noff;
                uint32_t off = n * 128 + (((kc + b_sub) ^ (n & 7)) << 4);
                ldmx4(bh[pn], Bh + off);
                ldmx4(bl[pn], Bl + off);
            }
            #pragma unroll
            for (int mi = 0; mi < 2; mi++)
                #pragma unroll
                for (int ni = 0; ni < 8; ni++) {
                    const uint32_t* bf = &bh[ni >> 1][(ni & 1) * 2];
                    const uint32_t* lf = &bl[ni >> 1][(ni & 1) * 2];
                    mma_bf16(acc[mi][ni], ah[mi], bf);
                    mma_bf16(acc[mi][ni], al[mi], bf);
                    mma_bf16(acc[mi][ni], ah[mi], lf);
                }
        }
        __syncthreads();
    }

    const int tr = lane >> 2, tc = (lane & 3) * 2;
    const int rbase = m0 + wm * 32;
    const int cbase = n0 + wn * 64;
    #pragma unroll
    for (int mi = 0; mi < 2; mi++) {
        #pragma unroll
        for (int ni = 0; ni < 8; ni++) {
            int col = cbase + ni * 8 + tc;
            int r0 = rbase + mi * 16 + tr;
            if (Chi) {
                uint32_t h0, l0, h1, l1;
                split_pack(acc[mi][ni][0], acc[mi][ni][1], h0, l0);
                split_pack(acc[mi][ni][2], acc[mi][ni][3], h1, l1);
                *(uint32_t*)(Chi + (size_t)r0 * N + col)       = h0;
                *(uint32_t*)(Clo + (size_t)r0 * N + col)       = l0;
                *(uint32_t*)(Chi + (size_t)(r0 + 8) * N + col) = h1;
                *(uint32_t*)(Clo + (size_t)(r0 + 8) * N + col) = l1;
            } else {
                float bx = 0.f, by = 0.f;
                if (bias) { float2 bv = *(const float2*)(bias + col); bx = bv.x; by = bv.y; }
                float2 v0; v0.x = acc[mi][ni][0] + bx; v0.y = acc[mi][ni][1] + by;
                *(float2*)(Cf + (size_t)r0 * N + col) = v0;
                float2 v1; v1.x = acc[mi][ni][2] + bx; v1.y = acc[mi][ni][3] + by;
                *(float2*)(Cf + (size_t)(r0 + 8) * N + col) = v1;
            }
        }
    }
}

// ============================================================================
// W_ep[bh][d][e] = (1/8) * sum_g rq[b,g,h*64+d] * rk[b,g,h*64+e]
// ============================================================================
#define AP 68

__global__ __launch_bounds__(256)
void wep_kernel(const float* __restrict__ RQ, const float* __restrict__ RK,
                float* __restrict__ WEP)
{
    __shared__ float sA[64 * AP];
    __shared__ float sB[64 * AP];
    const int tid = threadIdx.x;
    const int bh  = blockIdx.x;
    const int b   = bh >> 4, h = bh & 15;
    const int ldr = tid >> 2;
    const int lds = (tid & 3) * 16;
    const float* rqg = RQ + (size_t)(b * NG) * D_MODEL + h * DH;
    const float* rkg = RK + (size_t)(b * NG) * D_MODEL + h * DH;
    #pragma unroll
    for (int s = 0; s < 4; s++) {
        *(float4*)&sA[ldr * AP + lds + s * 4] =
            *(const float4*)(rqg + (size_t)ldr * D_MODEL + lds + s * 4);
        *(float4*)&sB[ldr * AP + lds + s * 4] =
            *(const float4*)(rkg + (size_t)ldr * D_MODEL + lds + s * 4);
    }
    __syncthreads();
    const int tRow = (tid >> 4) * 4;
    const int tCol = (tid & 15) * 4;
    float acc[4][4] = {};
    #pragma unroll 8
    for (int g = 0; g < 64; g++) {
        float rm[4], rn[4];
        #pragma unroll
        for (int i = 0; i < 4; i++) rm[i] = sA[g * AP + tRow + i];
        #pragma unroll
        for (int j = 0; j < 4; j++) rn[j] = sB[g * AP + tCol + j];
        #pragma unroll
        for (int i = 0; i < 4; i++)
            #pragma unroll
            for (int j = 0; j < 4; j++)
                acc[i][j] += rm[i] * rn[j];
    }
    float* wout = WEP + (size_t)bh * (DH * DH);
    #pragma unroll
    for (int i = 0; i < 4; i++)
        #pragma unroll
        for (int j = 0; j < 4; j++)
            wout[(tRow + i) * DH + tCol + j] = acc[i][j] * 0.125f;
}

// ============================================================================
// K'[bh][s][d] = sum_e K[b][s][h*64+e] * WEP[bh][d][e]  -> hi/lo bf16
// ============================================================================
__global__ __launch_bounds__(256)
void kprime_kernel(const float* __restrict__ Kp, const float* __restrict__ WEP,
                   bf16* __restrict__ KPhi, bf16* __restrict__ KPlo)
{
    __shared__ float sK[64 * AP];
    __shared__ float sW[64 * AP];
    const int tid = threadIdx.x;
    const int st  = blockIdx.x;
    const int bh  = blockIdx.y;
    const int b   = bh >> 4, h = bh & 15;
    const int s0  = st * 64;
    const int ldr = tid >> 2;
    const int lds = (tid & 3) * 16;

    const float* kg = Kp + (size_t)(b * NL + s0) * D_MODEL + h * DH;
    const float* wg = WEP + (size_t)bh * (DH * DH);
    #pragma unroll
    for (int s = 0; s < 4; s++) {
        *(float4*)&sK[ldr * AP + lds + s * 4] =
            *(const float4*)(kg + (size_t)ldr * D_MODEL + lds + s * 4);
        *(float4*)&sW[ldr * AP + lds + s * 4] =
            *(const float4*)(wg + ldr * DH + lds + s * 4);
    }
    __syncthreads();

    const int tRow = (tid >> 4) * 4;
    const int tCol = (tid & 15) * 4;
    float acc[4][4] = {};
    #pragma unroll 8
    for (int e = 0; e < 64; e++) {
        float rm[4], rn[4];
        #pragma unroll
        for (int i = 0; i < 4; i++) rm[i] = sK[(tRow + i) * AP + e];
        #pragma unroll
        for (int j = 0; j < 4; j++) rn[j] = sW[(tCol + j) * AP + e];
        #pragma unroll
        for (int i = 0; i < 4; i++)
            #pragma unroll
            for (int j = 0; j < 4; j++)
                acc[i][j] += rm[i] * rn[j];
    }
    #pragma unroll
    for (int i = 0; i < 4; i++) {
        size_t o = (size_t)(bh * NL + s0 + tRow + i) * DH + tCol;
        uint32_t h0, l0, h1, l1;
        split_pack(acc[i][0], acc[i][1], h0, l0);
        split_pack(acc[i][2], acc[i][3], h1, l1);
        *(uint32_t*)(KPhi + o)     = h0;  *(uint32_t*)(KPlo + o)     = l0;
        *(uint32_t*)(KPhi + o + 2) = h1;  *(uint32_t*)(KPlo + o + 2) = l1;
    }
}

// ============================================================================
// Flash attention, mma.sync split-bf16, transposed hi/lo output.
// ============================================================================
#define ATT_STAGE 32768
#define ATT_SMEM  (2 * ATT_STAGE + 32768)

__global__ __launch_bounds__(256, 1)
void attn_mma_kernel(const bf16* __restrict__ Qhi, const bf16* __restrict__ Qlo,
                     const bf16* __restrict__ KPhi, const bf16* __restrict__ KPlo,
                     const bf16* __restrict__ Vhi, const bf16* __restrict__ Vlo,
                     bf16* __restrict__ OThi, bf16* __restrict__ OTlo)
{
    extern __shared__ char smem[];
    const uint32_t sb = smem_u32(smem);
    const uint32_t QH = sb + 2 * ATT_STAGE, QL = QH + 16384;
    const int tid = threadIdx.x;
    const int wid = tid >> 5, lane = tid & 31;
    const int mt = blockIdx.x;
    const int bh = blockIdx.y;
    const int b = bh >> 4, h = bh & 15;
    const int l0 = mt * 128;

    {
        const bf16* qh = Qhi + (size_t)(b * NL + l0) * D_MODEL + h * DH;
        const bf16* ql = Qlo + (size_t)(b * NL + l0) * D_MODEL + h * DH;
        #pragma unroll
        for (int i = 0; i < 4; i++) {
            int u = tid + i * 256;
            int row = u >> 3, c8 = u & 7;
            uint32_t sw = row * 128 + ((c8 ^ (row & 7)) << 4);
            CP_ASYNC16(QH + sw, qh + (size_t)row * D_MODEL + c8 * 8);
            CP_ASYNC16(QL + sw, ql + (size_t)row * D_MODEL + c8 * 8);
        }
        CP_COMMIT();
    }

    const bf16* kph = KPhi + (size_t)bh * NL * DH;
    const bf16* kpl = KPlo + (size_t)bh * NL * DH;
    const bf16* vh  = Vhi + (size_t)b * NL * D_MODEL + h * DH;
    const bf16* vl  = Vlo + (size_t)b * NL * D_MODEL + h * DH;

    auto issue_stage = [&](int nc, int s) {
        const uint32_t stb = sb + s * ATT_STAGE;
        #pragma unroll
        for (int i = 0; i < 2; i++) {
            int u = tid + i * 256;
            int row = u >> 3, c8 = u & 7;
            uint32_t sw = row * 128 + ((c8 ^ (row & 7)) << 4);
            CP_ASYNC16(stb + sw,         kph + (size_t)(nc * 64 + row) * DH + c8 * 8);
            CP_ASYNC16(stb + 8192 + sw,  kpl + (size_t)(nc * 64 + row) * DH + c8 * 8);
            CP_ASYNC16(stb + 16384 + sw, vh + (size_t)(nc * 64 + row) * D_MODEL + c8 * 8);
            CP_ASYNC16(stb + 24576 + sw, vl + (size_t)(nc * 64 + row) * D_MODEL + c8 * 8);
        }
        CP_COMMIT();
    };

    issue_stage(0, 0);
    CP_WAIT(1);
    __syncthreads();

    // ---- hoist Q fragments (A-operand lane map)
    uint32_t qh[4][4], ql[4][4];
    const int r0 = wid * 16;
    const int frow = r0 + (lane & 15);
    const int fsub = lane >> 4;
    #pragma unroll
    for (int kk = 0; kk < 4; kk++) {
        uint32_t off = frow * 128 + (((kk * 2 + fsub) ^ (frow & 7)) << 4);
        ldmx4(qh[kk], QH + off);
        ldmx4(ql[kk], QL + off);
    }

    // B-operand lane map (same as the proven GEMM kernel)
    const int g      = lane >> 3;
    const int b_noff = ((g & 2) << 2) + (lane & 7);
    const int b_sub  = g & 1;

    float mM[2] = { -1e30f, -1e30f }, lS[2] = { 0.f, 0.f };
    float o[8][4] = {};

    for (int nc = 0; nc < 16; nc++) {
        if (nc + 1 < 16) { issue_stage(nc + 1, (nc + 1) & 1); CP_WAIT(1); }
        else             { CP_WAIT(0); }
        __syncthreads();
        const uint32_t stb = sb + (nc & 1) * ATT_STAGE;

        // ---- scores: S[m16][n64], 3-term split (FIXED B fragment map)
        float sc[8][4] = {};
        #pragma unroll
        for (int kk = 0; kk < 4; kk++) {
            uint32_t kb[4][4], klo[4][4];
            #pragma unroll
            for (int ng = 0; ng < 4; ng++) {
                int nr = ng * 16 + b_noff;
                uint32_t off = nr * 128 + (((kk * 2 + b_sub) ^ (nr & 7)) << 4);
                ldmx4(kb[ng], stb + off);
                ldmx4(klo[ng], stb + 8192 + off);
            }
            #pragma unroll
            for (int ng = 0; ng < 4; ng++)
                #pragma unroll
                for (int hf = 0; hf < 2; hf++) {
                    float* a = sc[ng * 2 + hf];
                    mma_bf16(a, qh[kk], &kb[ng][hf * 2]);
                    mma_bf16(a, ql[kk], &kb[ng][hf * 2]);
                    mma_bf16(a, qh[kk], &klo[ng][hf * 2]);
                }
        }

        // ---- online softmax
        float rmax0 = -1e30f, rmax1 = -1e30f;
        #pragma unroll
        for (int t = 0; t < 8; t++) {
            rmax0 = fmaxf(rmax0, fmaxf(sc[t][0], sc[t][1]));
            rmax1 = fmaxf(rmax1, fmaxf(sc[t][2], sc[t][3]));
        }
        #pragma unroll
        for (int off = 1; off <= 2; off <<= 1) {
            rmax0 = fmaxf(rmax0, __shfl_xor_sync(0xffffffffu, rmax0, off));
            rmax1 = fmaxf(rmax1, __shfl_xor_sync(0xffffffffu, rmax1, off));
        }
        float nM0 = fmaxf(mM[0], rmax0), nM1 = fmaxf(mM[1], rmax1);
        float cor0 = __expf(mM[0] - nM0), cor1 = __expf(mM[1] - nM1);
        mM[0] = nM0; mM[1] = nM1;

        uint32_t php[8][2], plp[8][2];
        float ps0 = 0.f, ps1 = 0.f;
        #pragma unroll
        for (int t = 0; t < 8; t++) {
            float p0 = __expf(sc[t][0] - nM0), p1 = __expf(sc[t][1] - nM0);
            float p2 = __expf(sc[t][2] - nM1), p3 = __expf(sc[t][3] - nM1);
            ps0 += p0 + p1; ps1 += p2 + p3;
            split_pack(p0, p1, php[t][0], plp[t][0]);
            split_pack(p2, p3, php[t][1], plp[t][1]);
        }
        #pragma unroll
        for (int off = 1; off <= 2; off <<= 1) {
            ps0 += __shfl_xor_sync(0xffffffffu, ps0, off);
            ps1 += __shfl_xor_sync(0xffffffffu, ps1, off);
        }
        lS[0] = lS[0] * cor0 + ps0;
        lS[1] = lS[1] * cor1 + ps1;
        #pragma unroll
        for (int t = 0; t < 8; t++) {
            o[t][0] *= cor0; o[t][1] *= cor0;
            o[t][2] *= cor1; o[t][3] *= cor1;
        }

        // ---- PV: O[m16][d64] += P[m16][s64] V[s64][d64]
        #pragma unroll
        for (int kk = 0; kk < 4; kk++) {
            uint32_t vb[4][4], vlo[4][4];
            #pragma unroll
            for (int ng = 0; ng < 4; ng++) {
                int srow = kk * 16 + (lane & 7) + 8 * ((lane >> 3) & 1);
                uint32_t c8 = 2 * ng + (lane >> 4);
                uint32_t off = srow * 128 + ((c8 ^ (srow & 7)) << 4);
                ldmx4t(vb[ng], stb + 16384 + off);
                ldmx4t(vlo[ng], stb + 24576 + off);
            }
            uint32_t pa[4]  = { php[2 * kk][0], php[2 * kk][1], php[2 * kk + 1][0], php[2 * kk + 1][1] };
            uint32_t pal[4] = { plp[2 * kk][0], plp[2 * kk][1], plp[2 * kk + 1][0], plp[2 * kk + 1][1] };
            #pragma unroll
            for (int ng = 0; ng < 4; ng++)
                #pragma unroll
                for (int hf = 0; hf < 2; hf++) {
                    float* c = o[ng * 2 + hf];
                    mma_bf16(c, pa, &vb[ng][hf * 2]);
                    mma_bf16(c, pal, &vb[ng][hf * 2]);
                    mma_bf16(c, pa, &vlo[ng][hf * 2]);
                }
        }
        __syncthreads();
    }

    // ---- normalize + transpose through smem (fp32 [d][m], pitch 132)
    float inv0 = 1.0f / lS[0], inv1 = 1.0f / lS[1];
    float* sOT = (float*)smem;
    const int orow = lane >> 2, ocol = (lane & 3) * 2;
    #pragma unroll
    for (int t = 0; t < 8; t++) {
        int d = t * 8 + ocol;
        sOT[(d + 0) * 132 + r0 + orow]     = o[t][0] * inv0;
        sOT[(d + 1) * 132 + r0 + orow]     = o[t][1] * inv0;
        sOT[(d + 0) * 132 + r0 + orow + 8] = o[t][2] * inv1;
        sOT[(d + 1) * 132 + r0 + orow + 8] = o[t][3] * inv1;
    }
    __syncthreads();

    {
        const int d = tid >> 2;
        const int mseg = (tid & 3) * 32;
        size_t gro = (size_t)(b * NL + h * DH + d) * NL + l0 + mseg;
        #pragma unroll
        for (int j = 0; j < 32; j += 2) {
            float f0 = sOT[d * 132 + mseg + j];
            float f1 = sOT[d * 132 + mseg + j + 1];
            uint32_t hp, lp;
            split_pack(f0, f1, hp, lp);
            *(uint32_t*)(OThi + gro + j) = hp;
            *(uint32_t*)(OTlo + gro + j) = lp;
        }
    }
}

// ============================================================================
// Launch
// ============================================================================
extern "C" void kernel_launch(void* const* d_in, const int* in_sizes, int n_in,
                              void* d_out, int out_size)
{
    const float* queries = (const float*)d_in[0];
    const float* keys    = (const float*)d_in[1];
    const float* values  = (const float*)d_in[2];
    const float* routers = (const float*)d_in[3];
    const float* Wq      = (const float*)d_in[4];
    const float* Wk      = (const float*)d_in[5];
    const float* Wv      = (const float*)d_in[6];
    const float* Wlq     = (const float*)d_in[7];
    const float* Wlk     = (const float*)d_in[8];
    const float* Wo      = (const float*)d_in[9];
    const float* bo      = (const float*)d_in[10];
    float* out           = (float*)d_out;

    float *Kp, *RQ, *RK, *WEP;
    bf16 *Qhi, *Qlo, *Vhi, *Vlo, *KPhi, *KPlo, *OThi, *OTlo, *Ahi, *Alo, *Whi, *Wlo;
    cudaGetSymbolAddress((void**)&Kp,   g_K);
    cudaGetSymbolAddress((void**)&RQ,   g_RQ);
    cudaGetSymbolAddress((void**)&RK,   g_RK);
    cudaGetSymbolAddress((void**)&WEP,  g_WEP);
    cudaGetSymbolAddress((void**)&Qhi,  g_Qhi);
    cudaGetSymbolAddress((void**)&Qlo,  g_Qlo);
    cudaGetSymbolAddress((void**)&Vhi,  g_Vhi);
    cudaGetSymbolAddress((void**)&Vlo,  g_Vlo);
    cudaGetSymbolAddress((void**)&KPhi, g_KPhi);
    cudaGetSymbolAddress((void**)&KPlo, g_KPlo);
    cudaGetSymbolAddress((void**)&OThi, g_OThi);
    cudaGetSymbolAddress((void**)&OTlo, g_OTlo);
    cudaGetSymbolAddress((void**)&Ahi,  g_Ahi);
    cudaGetSymbolAddress((void**)&Alo,  g_Alo);
    cudaGetSymbolAddress((void**)&Whi,  g_Whi);
    cudaGetSymbolAddress((void**)&Wlo,  g_Wlo);

    const int M  = NB * NL;
    const int Mr = NB * NG;
    const int N  = D_MODEL, K = D_MODEL;

    cudaFuncSetAttribute(gemm_mma_kernel,
                         cudaFuncAttributeMaxDynamicSharedMemorySize, GEMM_SMEM);
    cudaFuncSetAttribute(attn_mma_kernel,
                         cudaFuncAttributeMaxDynamicSharedMemorySize, ATT_SMEM);

    dim3 cw(32, 32);
    dim3 gBig(N / 128, M / 128);
    dim3 gRtr(N / 128, Mr / 128);
    const int nBig = M * K, nRtr = Mr * K;

    // Q projection -> hi/lo
    conv_hilo_kernel<<<nBig / 1024, 256>>>(queries, Ahi, Alo, nBig);
    conv_wt_kernel<<<cw, 256>>>(Wq, Whi, Wlo);
    gemm_mma_kernel<<<gBig, 256, GEMM_SMEM>>>(Ahi, Alo, Whi, Wlo, nullptr, nullptr, Qhi, Qlo, M, N, K);
    // K projection -> fp32
    conv_hilo_kernel<<<nBig / 1024, 256>>>(keys, Ahi, Alo, nBig);
    conv_wt_kernel<<<cw, 256>>>(Wk, Whi, Wlo);
    gemm_mma_kernel<<<gBig, 256, GEMM_SMEM>>>(Ahi, Alo, Whi, Wlo, Kp, nullptr, nullptr, nullptr, M, N, K);
    // V projection -> hi/lo
    conv_hilo_kernel<<<nBig / 1024, 256>>>(values, Ahi, Alo, nBig);
    conv_wt_kernel<<<cw, 256>>>(Wv, Whi, Wlo);
    gemm_mma_kernel<<<gBig, 256, GEMM_SMEM>>>(Ahi, Alo, Whi, Wlo, nullptr, nullptr, Vhi, Vlo, M, N, K);
    // router projections -> fp32
    conv_hilo_kernel<<<nRtr / 1024, 256>>>(routers, Ahi, Alo, nRtr);
    conv_wt_kernel<<<cw, 256>>>(Wlq, Whi, Wlo);
    gemm_mma_kernel<<<gRtr, 256, GEMM_SMEM>>>(Ahi, Alo, Whi, Wlo, RQ, nullptr, nullptr, nullptr, Mr, N, K);
    conv_wt_kernel<<<cw, 256>>>(Wlk, Whi, Wlo);
    gemm_mma_kernel<<<gRtr, 256, GEMM_SMEM>>>(Ahi, Alo, Whi, Wlo, RK, nullptr, nullptr, nullptr, Mr, N, K);

    // W_ep (scale folded), K' = K @ Wep^T -> hi/lo
    wep_kernel<<<NB * NH, 256>>>(RQ, RK, WEP);
    dim3 gKP(NL / 64, NB * NH);
    kprime_kernel<<<gKP, 256>>>(Kp, WEP, KPhi, KPlo);

    // flash attention (tensorized) -> OT hi/lo
    dim3 gAtt(NL / 128, NB * NH);
    attn_mma_kernel<<<gAtt, 256, ATT_SMEM>>>(Qhi, Qlo, KPhi, KPlo, Vhi, Vlo, OThi, OTlo);

    // final GEMM with bias
    conv_wt_kernel<<<cw, 256>>>(Wo, Whi, Wlo);
    gemm_mma_kernel<<<gBig, 256, GEMM_SMEM>>>(OThi, OTlo, Whi, Wlo, out, bo, nullptr, nullptr, M, N, K);
}

// round 6
// speedup vs baseline: 3.4878x; 1.1312x over previous
#include <cuda_runtime.h>
#include <cuda_bf16.h>
#include <cstdint>

// ============================================================================
// Shapes (fixed): B=8, L=S=1024, G=64, D=1024, H=16, d_head=64
// compute_103 PTX: no tcgen05; mma.sync bf16 with hi/lo split precision.
// This round: multi-stream fork/join (graph-capturable) + 3-stage GEMM pipe.
// ============================================================================

#define D_MODEL 1024
#define NB 8
#define NL 1024
#define NG 64
#define NH 16
#define DH 64

typedef __nv_bfloat16 bf16;

// -------------------- scratch (device globals; no allocation) ---------------
__device__ float g_K  [NB * NL * D_MODEL];           // projected K fp32
__device__ float g_RQ [NB * NG * D_MODEL];
__device__ float g_RK [NB * NG * D_MODEL];
__device__ float g_WEP[NB * NH * DH * DH];
// per-chain activation planes
__device__ bf16 g_QAhi[NB * NL * D_MODEL];
__device__ bf16 g_QAlo[NB * NL * D_MODEL];
__device__ bf16 g_KAhi[NB * NL * D_MODEL];
__device__ bf16 g_KAlo[NB * NL * D_MODEL];
__device__ bf16 g_VAhi[NB * NL * D_MODEL];
__device__ bf16 g_VAlo[NB * NL * D_MODEL];
__device__ bf16 g_RAhi[NB * NG * D_MODEL];
__device__ bf16 g_RAlo[NB * NG * D_MODEL];
// per-chain weight planes (transposed [n][k])
__device__ bf16 g_WQhi[D_MODEL * D_MODEL];
__device__ bf16 g_WQlo[D_MODEL * D_MODEL];
__device__ bf16 g_WKhi[D_MODEL * D_MODEL];
__device__ bf16 g_WKlo[D_MODEL * D_MODEL];
__device__ bf16 g_WVhi[D_MODEL * D_MODEL];
__device__ bf16 g_WVlo[D_MODEL * D_MODEL];
__device__ bf16 g_WLQhi[D_MODEL * D_MODEL];
__device__ bf16 g_WLQlo[D_MODEL * D_MODEL];
__device__ bf16 g_WLKhi[D_MODEL * D_MODEL];
__device__ bf16 g_WLKlo[D_MODEL * D_MODEL];
__device__ bf16 g_WOhi[D_MODEL * D_MODEL];
__device__ bf16 g_WOlo[D_MODEL * D_MODEL];
// intermediates
__device__ bf16 g_Qhi[NB * NL * D_MODEL];
__device__ bf16 g_Qlo[NB * NL * D_MODEL];
__device__ bf16 g_Vhi[NB * NL * D_MODEL];
__device__ bf16 g_Vlo[NB * NL * D_MODEL];
__device__ bf16 g_KPhi[NB * NH * NL * DH];
__device__ bf16 g_KPlo[NB * NH * NL * DH];
__device__ bf16 g_OThi[NB * NL * D_MODEL];
__device__ bf16 g_OTlo[NB * NL * D_MODEL];

// ============================================================================
// PTX helpers
// ============================================================================
__device__ __forceinline__ uint32_t smem_u32(const void* p) {
    uint32_t a;
    asm("{ .reg .u64 t; cvta.to.shared.u64 t, %1; cvt.u32.u64 %0, t; }" : "=r"(a) : "l"(p));
    return a;
}
#define CP_ASYNC16(dst, src) \
    asm volatile("cp.async.cg.shared.global [%0], [%1], 16;" :: "r"(dst), "l"(src))
#define CP_COMMIT() asm volatile("cp.async.commit_group;" ::: "memory")
#define CP_WAIT(n)  asm volatile("cp.async.wait_group %0;" :: "n"(n) : "memory")

__device__ __forceinline__ void ldmx4(uint32_t* r, uint32_t addr) {
    asm volatile("ldmatrix.sync.aligned.m8n8.x4.shared.b16 {%0,%1,%2,%3}, [%4];"
                 : "=r"(r[0]), "=r"(r[1]), "=r"(r[2]), "=r"(r[3]) : "r"(addr));
}
__device__ __forceinline__ void ldmx4t(uint32_t* r, uint32_t addr) {
    asm volatile("ldmatrix.sync.aligned.m8n8.x4.trans.shared.b16 {%0,%1,%2,%3}, [%4];"
                 : "=r"(r[0]), "=r"(r[1]), "=r"(r[2]), "=r"(r[3]) : "r"(addr));
}
__device__ __forceinline__ void mma_bf16(float* c, const uint32_t* a, const uint32_t* b) {
    asm volatile(
        "mma.sync.aligned.m16n8k16.row.col.f32.bf16.bf16.f32 "
        "{%0,%1,%2,%3}, {%4,%5,%6,%7}, {%8,%9}, {%0,%1,%2,%3};"
        : "+f"(c[0]), "+f"(c[1]), "+f"(c[2]), "+f"(c[3])
        : "r"(a[0]), "r"(a[1]), "r"(a[2]), "r"(a[3]), "r"(b[0]), "r"(b[1]));
}
__device__ __forceinline__ uint32_t pack_bf16(float lo, float hi) {
    __nv_bfloat162 p = __floats2bfloat162_rn(lo, hi);
    return *(uint32_t*)&p;
}
__device__ __forceinline__ void split_pack(float x, float y, uint32_t& hi, uint32_t& lo) {
    bf16 hx = __float2bfloat16_rn(x), hy = __float2bfloat16_rn(y);
    hi = pack_bf16(__bfloat162float(hx), __bfloat162float(hy));
    __nv_bfloat162 hp; *(uint32_t*)&hp = hi;
    lo = pack_bf16(x - __bfloat162float(hp.x), y - __bfloat162float(hp.y));
}

// ============================================================================
// Conversion kernels
// ============================================================================
__global__ __launch_bounds__(256)
void conv_hilo_kernel(const float* __restrict__ in, bf16* __restrict__ hi,
                      bf16* __restrict__ lo, int n)
{
    int i = (blockIdx.x * 256 + threadIdx.x) * 4;
    if (i >= n) return;
    float4 v = *(const float4*)(in + i);
    uint32_t h0, l0, h1, l1;
    split_pack(v.x, v.y, h0, l0);
    split_pack(v.z, v.w, h1, l1);
    *(uint32_t*)(hi + i) = h0; *(uint32_t*)(hi + i + 2) = h1;
    *(uint32_t*)(lo + i) = l0; *(uint32_t*)(lo + i + 2) = l1;
}

__global__ __launch_bounds__(256)
void conv_wt_kernel(const float* __restrict__ W, bf16* __restrict__ th,
                    bf16* __restrict__ tl)
{
    __shared__ float t[32][33];
    int bn = blockIdx.x * 32, bk = blockIdx.y * 32;
    int tx = threadIdx.x & 31, ty = threadIdx.x >> 5;
    #pragma unroll
    for (int j = 0; j < 32; j += 8)
        t[ty + j][tx] = W[(size_t)(bk + ty + j) * D_MODEL + bn + tx];
    __syncthreads();
    #pragma unroll
    for (int j = 0; j < 32; j += 8) {
        float v = t[tx][ty + j];
        bf16 h = __float2bfloat16_rn(v);
        size_t o = (size_t)(bn + ty + j) * D_MODEL + bk + tx;
        th[o] = h;
        tl[o] = __float2bfloat16_rn(v - __bfloat162float(h));
    }
}

// ============================================================================
// mma.sync split-bf16 GEMM; 3-stage cp.async pipeline, one barrier per chunk.
// ============================================================================
#define ARR_BYTES   16384
#define STAGE_BYTES (4 * ARR_BYTES)
#define GEMM_SMEM   (3 * STAGE_BYTES)    // 196608

__global__ __launch_bounds__(256, 1)
void gemm_mma_kernel(const bf16* __restrict__ Ahi, const bf16* __restrict__ Alo,
                     const bf16* __restrict__ Bhi, const bf16* __restrict__ Blo,
                     float* __restrict__ Cf, const float* __restrict__ bias,
                     bf16* __restrict__ Chi, bf16* __restrict__ Clo,
                     int M, int N, int K)
{
    extern __shared__ char smem[];
    const uint32_t sbase = smem_u32(smem);
    const int tid  = threadIdx.x;
    const int wid  = tid >> 5, lane = tid & 31;
    const int wm   = wid & 3;
    const int wn   = wid >> 2;
    const int m0   = blockIdx.y * 128;
    const int n0   = blockIdx.x * 128;
    const int nchunks = K >> 6;

    const bf16* srcs[4] = { Ahi + (size_t)m0 * K, Alo + (size_t)m0 * K,
                            Bhi + (size_t)n0 * K, Blo + (size_t)n0 * K };

    auto issue = [&](int c, int s) {
        const uint32_t stb = sbase + s * STAGE_BYTES;
        #pragma unroll
        for (int a = 0; a < 4; a++) {
            const bf16* src = srcs[a] + c * 64;
            const uint32_t ab = stb + a * ARR_BYTES;
            #pragma unroll
            for (int i = 0; i < 4; i++) {
                int u   = tid + i * 256;
                int row = u >> 3, c8 = u & 7;
                uint32_t dst = ab + row * 128 + ((c8 ^ (row & 7)) << 4);
                CP_ASYNC16(dst, src + (size_t)row * K + c8 * 8);
            }
        }
        CP_COMMIT();
    };

    issue(0, 0);
    issue(1, 1);

    float acc[2][8][4] = {};
    const int a_row0 = wm * 32 + (lane & 15);
    const int a_sub  = lane >> 4;
    const int g      = lane >> 3;
    const int b_noff = ((g & 2) << 2) + (lane & 7);
    const int b_sub  = g & 1;

    for (int c = 0; c < nchunks; c++) {
        if (c + 1 < nchunks) CP_WAIT(1);
        else                 CP_WAIT(0);
        __syncthreads();                       // all warps done with slot (c+2)%3
        if (c + 2 < nchunks) issue(c + 2, (c + 2) % 3);

        const uint32_t stb = sbase + (c % 3) * STAGE_BYTES;
        const uint32_t Ah = stb, Al = stb + ARR_BYTES;
        const uint32_t Bh = stb + 2 * ARR_BYTES, Bl = stb + 3 * ARR_BYTES;

        #pragma unroll
        for (int k16 = 0; k16 < 4; k16++) {
            const int kc = k16 * 2;
            uint32_t ah[2][4], al[2][4], bh[4][4], bl[4][4];
            #pragma unroll
            for (int mi = 0; mi < 2; mi++) {
                int row = a_row0 + mi * 16;
                uint32_t off = row * 128 + (((kc + a_sub) ^ (row & 7)) << 4);
                ldmx4(ah[mi], Ah + off);
                ldmx4(al[mi], Al + off);
            }
            #pragma unroll
            for (int pn = 0; pn < 4; pn++) {
                int n = wn * 64 + pn * 16 + b_noff;
                uint32_t off = n * 128 + (((kc + b_sub) ^ (n & 7)) << 4);
                ldmx4(bh[pn], Bh + off);
                ldmx4(bl[pn], Bl + off);
            }
            #pragma unroll
            for (int mi = 0; mi < 2; mi++)
                #pragma unroll
                for (int ni = 0; ni < 8; ni++) {
                    const uint32_t* bf = &bh[ni >> 1][(ni & 1) * 2];
                    const uint32_t* lf = &bl[ni >> 1][(ni & 1) * 2];
                    mma_bf16(acc[mi][ni], ah[mi], bf);
                    mma_bf16(acc[mi][ni], al[mi], bf);
                    mma_bf16(acc[mi][ni], ah[mi], lf);
                }
        }
    }

    const int tr = lane >> 2, tc = (lane & 3) * 2;
    const int rbase = m0 + wm * 32;
    const int cbase = n0 + wn * 64;
    #pragma unroll
    for (int mi = 0; mi < 2; mi++) {
        #pragma unroll
        for (int ni = 0; ni < 8; ni++) {
            int col = cbase + ni * 8 + tc;
            int r0 = rbase + mi * 16 + tr;
            if (Chi) {
                uint32_t h0, l0, h1, l1;
                split_pack(acc[mi][ni][0], acc[mi][ni][1], h0, l0);
                split_pack(acc[mi][ni][2], acc[mi][ni][3], h1, l1);
                *(uint32_t*)(Chi + (size_t)r0 * N + col)       = h0;
                *(uint32_t*)(Clo + (size_t)r0 * N + col)       = l0;
                *(uint32_t*)(Chi + (size_t)(r0 + 8) * N + col) = h1;
                *(uint32_t*)(Clo + (size_t)(r0 + 8) * N + col) = l1;
            } else {
                float bx = 0.f, by = 0.f;
                if (bias) { float2 bv = *(const float2*)(bias + col); bx = bv.x; by = bv.y; }
                float2 v0; v0.x = acc[mi][ni][0] + bx; v0.y = acc[mi][ni][1] + by;
                *(float2*)(Cf + (size_t)r0 * N + col) = v0;
                float2 v1; v1.x = acc[mi][ni][2] + bx; v1.y = acc[mi][ni][3] + by;
                *(float2*)(Cf + (size_t)(r0 + 8) * N + col) = v1;
            }
        }
    }
}

// ============================================================================
// W_ep[bh][d][e] = (1/8) * sum_g rq[b,g,h*64+d] * rk[b,g,h*64+e]
// ============================================================================
#define AP 68

__global__ __launch_bounds__(256)
void wep_kernel(const float* __restrict__ RQ, const float* __restrict__ RK,
                float* __restrict__ WEP)
{
    __shared__ float sA[64 * AP];
    __shared__ float sB[64 * AP];
    const int tid = threadIdx.x;
    const int bh  = blockIdx.x;
    const int b   = bh >> 4, h = bh & 15;
    const int ldr = tid >> 2;
    const int lds = (tid & 3) * 16;
    const float* rqg = RQ + (size_t)(b * NG) * D_MODEL + h * DH;
    const float* rkg = RK + (size_t)(b * NG) * D_MODEL + h * DH;
    #pragma unroll
    for (int s = 0; s < 4; s++) {
        *(float4*)&sA[ldr * AP + lds + s * 4] =
            *(const float4*)(rqg + (size_t)ldr * D_MODEL + lds + s * 4);
        *(float4*)&sB[ldr * AP + lds + s * 4] =
            *(const float4*)(rkg + (size_t)ldr * D_MODEL + lds + s * 4);
    }
    __syncthreads();
    const int tRow = (tid >> 4) * 4;
    const int tCol = (tid & 15) * 4;
    float acc[4][4] = {};
    #pragma unroll 8
    for (int g = 0; g < 64; g++) {
        float rm[4], rn[4];
        #pragma unroll
        for (int i = 0; i < 4; i++) rm[i] = sA[g * AP + tRow + i];
        #pragma unroll
        for (int j = 0; j < 4; j++) rn[j] = sB[g * AP + tCol + j];
        #pragma unroll
        for (int i = 0; i < 4; i++)
            #pragma unroll
            for (int j = 0; j < 4; j++)
                acc[i][j] += rm[i] * rn[j];
    }
    float* wout = WEP + (size_t)bh * (DH * DH);
    #pragma unroll
    for (int i = 0; i < 4; i++)
        #pragma unroll
        for (int j = 0; j < 4; j++)
            wout[(tRow + i) * DH + tCol + j] = acc[i][j] * 0.125f;
}

// ============================================================================
// K'[bh][s][d] = sum_e K[b][s][h*64+e] * WEP[bh][d][e]  -> hi/lo bf16
// ============================================================================
__global__ __launch_bounds__(256)
void kprime_kernel(const float* __restrict__ Kp, const float* __restrict__ WEP,
                   bf16* __restrict__ KPhi, bf16* __restrict__ KPlo)
{
    __shared__ float sK[64 * AP];
    __shared__ float sW[64 * AP];
    const int tid = threadIdx.x;
    const int st  = blockIdx.x;
    const int bh  = blockIdx.y;
    const int b   = bh >> 4, h = bh & 15;
    const int s0  = st * 64;
    const int ldr = tid >> 2;
    const int lds = (tid & 3) * 16;

    const float* kg = Kp + (size_t)(b * NL + s0) * D_MODEL + h * DH;
    const float* wg = WEP + (size_t)bh * (DH * DH);
    #pragma unroll
    for (int s = 0; s < 4; s++) {
        *(float4*)&sK[ldr * AP + lds + s * 4] =
            *(const float4*)(kg + (size_t)ldr * D_MODEL + lds + s * 4);
        *(float4*)&sW[ldr * AP + lds + s * 4] =
            *(const float4*)(wg + ldr * DH + lds + s * 4);
    }
    __syncthreads();

    const int tRow = (tid >> 4) * 4;
    const int tCol = (tid & 15) * 4;
    float acc[4][4] = {};
    #pragma unroll 8
    for (int e = 0; e < 64; e++) {
        float rm[4], rn[4];
        #pragma unroll
        for (int i = 0; i < 4; i++) rm[i] = sK[(tRow + i) * AP + e];
        #pragma unroll
        for (int j = 0; j < 4; j++) rn[j] = sW[(tCol + j) * AP + e];
        #pragma unroll
        for (int i = 0; i < 4; i++)
            #pragma unroll
            for (int j = 0; j < 4; j++)
                acc[i][j] += rm[i] * rn[j];
    }
    #pragma unroll
    for (int i = 0; i < 4; i++) {
        size_t o = (size_t)(bh * NL + s0 + tRow + i) * DH + tCol;
        uint32_t h0, l0, h1, l1;
        split_pack(acc[i][0], acc[i][1], h0, l0);
        split_pack(acc[i][2], acc[i][3], h1, l1);
        *(uint32_t*)(KPhi + o)     = h0;  *(uint32_t*)(KPlo + o)     = l0;
        *(uint32_t*)(KPhi + o + 2) = h1;  *(uint32_t*)(KPlo + o + 2) = l1;
    }
}

// ============================================================================
// Flash attention, mma.sync split-bf16, transposed hi/lo output.
// ============================================================================
#define ATT_STAGE 32768
#define ATT_SMEM  (2 * ATT_STAGE + 32768)

__global__ __launch_bounds__(256, 1)
void attn_mma_kernel(const bf16* __restrict__ Qhi, const bf16* __restrict__ Qlo,
                     const bf16* __restrict__ KPhi, const bf16* __restrict__ KPlo,
                     const bf16* __restrict__ Vhi, const bf16* __restrict__ Vlo,
                     bf16* __restrict__ OThi, bf16* __restrict__ OTlo)
{
    extern __shared__ char smem[];
    const uint32_t sb = smem_u32(smem);
    const uint32_t QH = sb + 2 * ATT_STAGE, QL = QH + 16384;
    const int tid = threadIdx.x;
    const int wid = tid >> 5, lane = tid & 31;
    const int mt = blockIdx.x;
    const int bh = blockIdx.y;
    const int b = bh >> 4, h = bh & 15;
    const int l0 = mt * 128;

    {
        const bf16* qh = Qhi + (size_t)(b * NL + l0) * D_MODEL + h * DH;
        const bf16* ql = Qlo + (size_t)(b * NL + l0) * D_MODEL + h * DH;
        #pragma unroll
        for (int i = 0; i < 4; i++) {
            int u = tid + i * 256;
            int row = u >> 3, c8 = u & 7;
            uint32_t sw = row * 128 + ((c8 ^ (row & 7)) << 4);
            CP_ASYNC16(QH + sw, qh + (size_t)row * D_MODEL + c8 * 8);
            CP_ASYNC16(QL + sw, ql + (size_t)row * D_MODEL + c8 * 8);
        }
        CP_COMMIT();
    }

    const bf16* kph = KPhi + (size_t)bh * NL * DH;
    const bf16* kpl = KPlo + (size_t)bh * NL * DH;
    const bf16* vh  = Vhi + (size_t)b * NL * D_MODEL + h * DH;
    const bf16* vl  = Vlo + (size_t)b * NL * D_MODEL + h * DH;

    auto issue_stage = [&](int nc, int s) {
        const uint32_t stb = sb + s * ATT_STAGE;
        #pragma unroll
        for (int i = 0; i < 2; i++) {
            int u = tid + i * 256;
            int row = u >> 3, c8 = u & 7;
            uint32_t sw = row * 128 + ((c8 ^ (row & 7)) << 4);
            CP_ASYNC16(stb + sw,         kph + (size_t)(nc * 64 + row) * DH + c8 * 8);
            CP_ASYNC16(stb + 8192 + sw,  kpl + (size_t)(nc * 64 + row) * DH + c8 * 8);
            CP_ASYNC16(stb + 16384 + sw, vh + (size_t)(nc * 64 + row) * D_MODEL + c8 * 8);
            CP_ASYNC16(stb + 24576 + sw, vl + (size_t)(nc * 64 + row) * D_MODEL + c8 * 8);
        }
        CP_COMMIT();
    };

    issue_stage(0, 0);
    CP_WAIT(1);
    __syncthreads();

    uint32_t qh[4][4], ql[4][4];
    const int r0 = wid * 16;
    const int frow = r0 + (lane & 15);
    const int fsub = lane >> 4;
    #pragma unroll
    for (int kk = 0; kk < 4; kk++) {
        uint32_t off = frow * 128 + (((kk * 2 + fsub) ^ (frow & 7)) << 4);
        ldmx4(qh[kk], QH + off);
        ldmx4(ql[kk], QL + off);
    }

    const int g      = lane >> 3;
    const int b_noff = ((g & 2) << 2) + (lane & 7);
    const int b_sub  = g & 1;

    float mM[2] = { -1e30f, -1e30f }, lS[2] = { 0.f, 0.f };
    float o[8][4] = {};

    for (int nc = 0; nc < 16; nc++) {
        if (nc + 1 < 16) { issue_stage(nc + 1, (nc + 1) & 1); CP_WAIT(1); }
        else             { CP_WAIT(0); }
        __syncthreads();
        const uint32_t stb = sb + (nc & 1) * ATT_STAGE;

        float sc[8][4] = {};
        #pragma unroll
        for (int kk = 0; kk < 4; kk++) {
            uint32_t kb[4][4], klo[4][4];
            #pragma unroll
            for (int ng = 0; ng < 4; ng++) {
                int nr = ng * 16 + b_noff;
                uint32_t off = nr * 128 + (((kk * 2 + b_sub) ^ (nr & 7)) << 4);
                ldmx4(kb[ng], stb + off);
                ldmx4(klo[ng], stb + 8192 + off);
            }
            #pragma unroll
            for (int ng = 0; ng < 4; ng++)
                #pragma unroll
                for (int hf = 0; hf < 2; hf++) {
                    float* a = sc[ng * 2 + hf];
                    mma_bf16(a, qh[kk], &kb[ng][hf * 2]);
                    mma_bf16(a, ql[kk], &kb[ng][hf * 2]);
                    mma_bf16(a, qh[kk], &klo[ng][hf * 2]);
                }
        }

        float rmax0 = -1e30f, rmax1 = -1e30f;
        #pragma unroll
        for (int t = 0; t < 8; t++) {
            rmax0 = fmaxf(rmax0, fmaxf(sc[t][0], sc[t][1]));
            rmax1 = fmaxf(rmax1, fmaxf(sc[t][2], sc[t][3]));
        }
        #pragma unroll
        for (int off = 1; off <= 2; off <<= 1) {
            rmax0 = fmaxf(rmax0, __shfl_xor_sync(0xffffffffu, rmax0, off));
            rmax1 = fmaxf(rmax1, __shfl_xor_sync(0xffffffffu, rmax1, off));
        }
        float nM0 = fmaxf(mM[0], rmax0), nM1 = fmaxf(mM[1], rmax1);
        float cor0 = __expf(mM[0] - nM0), cor1 = __expf(mM[1] - nM1);
        mM[0] = nM0; mM[1] = nM1;

        uint32_t php[8][2], plp[8][2];
        float ps0 = 0.f, ps1 = 0.f;
        #pragma unroll
        for (int t = 0; t < 8; t++) {
            float p0 = __expf(sc[t][0] - nM0), p1 = __expf(sc[t][1] - nM0);
            float p2 = __expf(sc[t][2] - nM1), p3 = __expf(sc[t][3] - nM1);
            ps0 += p0 + p1; ps1 += p2 + p3;
            split_pack(p0, p1, php[t][0], plp[t][0]);
            split_pack(p2, p3, php[t][1], plp[t][1]);
        }
        #pragma unroll
        for (int off = 1; off <= 2; off <<= 1) {
            ps0 += __shfl_xor_sync(0xffffffffu, ps0, off);
            ps1 += __shfl_xor_sync(0xffffffffu, ps1, off);
        }
        lS[0] = lS[0] * cor0 + ps0;
        lS[1] = lS[1] * cor1 + ps1;
        #pragma unroll
        for (int t = 0; t < 8; t++) {
            o[t][0] *= cor0; o[t][1] *= cor0;
            o[t][2] *= cor1; o[t][3] *= cor1;
        }

        #pragma unroll
        for (int kk = 0; kk < 4; kk++) {
            uint32_t vb[4][4], vlo[4][4];
            #pragma unroll
            for (int ng = 0; ng < 4; ng++) {
                int srow = kk * 16 + (lane & 7) + 8 * ((lane >> 3) & 1);
                uint32_t c8 = 2 * ng + (lane >> 4);
                uint32_t off = srow * 128 + ((c8 ^ (srow & 7)) << 4);
                ldmx4t(vb[ng], stb + 16384 + off);
                ldmx4t(vlo[ng], stb + 24576 + off);
            }
            uint32_t pa[4]  = { php[2 * kk][0], php[2 * kk][1], php[2 * kk + 1][0], php[2 * kk + 1][1] };
            uint32_t pal[4] = { plp[2 * kk][0], plp[2 * kk][1], plp[2 * kk + 1][0], plp[2 * kk + 1][1] };
            #pragma unroll
            for (int ng = 0; ng < 4; ng++)
                #pragma unroll
                for (int hf = 0; hf < 2; hf++) {
                    float* c = o[ng * 2 + hf];
                    mma_bf16(c, pa, &vb[ng][hf * 2]);
                    mma_bf16(c, pal, &vb[ng][hf * 2]);
                    mma_bf16(c, pa, &vlo[ng][hf * 2]);
                }
        }
        __syncthreads();
    }

    float inv0 = 1.0f / lS[0], inv1 = 1.0f / lS[1];
    float* sOT = (float*)smem;
    const int orow = lane >> 2, ocol = (lane & 3) * 2;
    #pragma unroll
    for (int t = 0; t < 8; t++) {
        int d = t * 8 + ocol;
        sOT[(d + 0) * 132 + r0 + orow]     = o[t][0] * inv0;
        sOT[(d + 1) * 132 + r0 + orow]     = o[t][1] * inv0;
        sOT[(d + 0) * 132 + r0 + orow + 8] = o[t][2] * inv1;
        sOT[(d + 1) * 132 + r0 + orow + 8] = o[t][3] * inv1;
    }
    __syncthreads();

    {
        const int d = tid >> 2;
        const int mseg = (tid & 3) * 32;
        size_t gro = (size_t)(b * NL + h * DH + d) * NL + l0 + mseg;
        #pragma unroll
        for (int j = 0; j < 32; j += 2) {
            float f0 = sOT[d * 132 + mseg + j];
            float f1 = sOT[d * 132 + mseg + j + 1];
            uint32_t hp, lp;
            split_pack(f0, f1, hp, lp);
            *(uint32_t*)(OThi + gro + j) = hp;
            *(uint32_t*)(OTlo + gro + j) = lp;
        }
    }
}

// ============================================================================
// Launch — multi-stream fork/join (graph-capture-safe)
// ============================================================================
extern "C" void kernel_launch(void* const* d_in, const int* in_sizes, int n_in,
                              void* d_out, int out_size)
{
    const float* queries = (const float*)d_in[0];
    const float* keys    = (const float*)d_in[1];
    const float* values  = (const float*)d_in[2];
    const float* routers = (const float*)d_in[3];
    const float* Wq      = (const float*)d_in[4];
    const float* Wk      = (const float*)d_in[5];
    const float* Wv      = (const float*)d_in[6];
    const float* Wlq     = (const float*)d_in[7];
    const float* Wlk     = (const float*)d_in[8];
    const float* Wo      = (const float*)d_in[9];
    const float* bo      = (const float*)d_in[10];
    float* out           = (float*)d_out;

    float *Kp, *RQ, *RK, *WEP;
    bf16 *QAhi, *QAlo, *KAhi, *KAlo, *VAhi, *VAlo, *RAhi, *RAlo;
    bf16 *WQhi, *WQlo, *WKhi, *WKlo, *WVhi, *WVlo, *WLQhi, *WLQlo, *WLKhi, *WLKlo, *WOhi, *WOlo;
    bf16 *Qhi, *Qlo, *Vhi, *Vlo, *KPhi, *KPlo, *OThi, *OTlo;
    cudaGetSymbolAddress((void**)&Kp,    g_K);
    cudaGetSymbolAddress((void**)&RQ,    g_RQ);
    cudaGetSymbolAddress((void**)&RK,    g_RK);
    cudaGetSymbolAddress((void**)&WEP,   g_WEP);
    cudaGetSymbolAddress((void**)&QAhi,  g_QAhi);
    cudaGetSymbolAddress((void**)&QAlo,  g_QAlo);
    cudaGetSymbolAddress((void**)&KAhi,  g_KAhi);
    cudaGetSymbolAddress((void**)&KAlo,  g_KAlo);
    cudaGetSymbolAddress((void**)&VAhi,  g_VAhi);
    cudaGetSymbolAddress((void**)&VAlo,  g_VAlo);
    cudaGetSymbolAddress((void**)&RAhi,  g_RAhi);
    cudaGetSymbolAddress((void**)&RAlo,  g_RAlo);
    cudaGetSymbolAddress((void**)&WQhi,  g_WQhi);
    cudaGetSymbolAddress((void**)&WQlo,  g_WQlo);
    cudaGetSymbolAddress((void**)&WKhi,  g_WKhi);
    cudaGetSymbolAddress((void**)&WKlo,  g_WKlo);
    cudaGetSymbolAddress((void**)&WVhi,  g_WVhi);
    cudaGetSymbolAddress((void**)&WVlo,  g_WVlo);
    cudaGetSymbolAddress((void**)&WLQhi, g_WLQhi);
    cudaGetSymbolAddress((void**)&WLQlo, g_WLQlo);
    cudaGetSymbolAddress((void**)&WLKhi, g_WLKhi);
    cudaGetSymbolAddress((void**)&WLKlo, g_WLKlo);
    cudaGetSymbolAddress((void**)&WOhi,  g_WOhi);
    cudaGetSymbolAddress((void**)&WOlo,  g_WOlo);
    cudaGetSymbolAddress((void**)&Qhi,   g_Qhi);
    cudaGetSymbolAddress((void**)&Qlo,   g_Qlo);
    cudaGetSymbolAddress((void**)&Vhi,   g_Vhi);
    cudaGetSymbolAddress((void**)&Vlo,   g_Vlo);
    cudaGetSymbolAddress((void**)&KPhi,  g_KPhi);
    cudaGetSymbolAddress((void**)&KPlo,  g_KPlo);
    cudaGetSymbolAddress((void**)&OThi,  g_OThi);
    cudaGetSymbolAddress((void**)&OTlo,  g_OTlo);

    const int M  = NB * NL;
    const int Mr = NB * NG;
    const int N  = D_MODEL, K = D_MODEL;

    cudaFuncSetAttribute(gemm_mma_kernel,
                         cudaFuncAttributeMaxDynamicSharedMemorySize, GEMM_SMEM);
    cudaFuncSetAttribute(attn_mma_kernel,
                         cudaFuncAttributeMaxDynamicSharedMemorySize, ATT_SMEM);

    // streams/events created once; work per call is identical & deterministic
    static cudaStream_t s1 = nullptr, s2 = nullptr, s3 = nullptr;
    static cudaEvent_t ev0 = nullptr, evQ = nullptr, evV = nullptr,
                       evR = nullptr, evWo = nullptr;
    if (!s1) {
        cudaStreamCreateWithFlags(&s1, cudaStreamNonBlocking);
        cudaStreamCreateWithFlags(&s2, cudaStreamNonBlocking);
        cudaStreamCreateWithFlags(&s3, cudaStreamNonBlocking);
        cudaEventCreateWithFlags(&ev0, cudaEventDisableTiming);
        cudaEventCreateWithFlags(&evQ, cudaEventDisableTiming);
        cudaEventCreateWithFlags(&evV, cudaEventDisableTiming);
        cudaEventCreateWithFlags(&evR, cudaEventDisableTiming);
        cudaEventCreateWithFlags(&evWo, cudaEventDisableTiming);
    }

    dim3 cw(32, 32);
    dim3 gBig(N / 128, M / 128);
    dim3 gRtr(N / 128, Mr / 128);
    const int nBig = M * K, nRtr = Mr * K;

    // fork
    cudaEventRecord(ev0, 0);
    cudaStreamWaitEvent(s1, ev0, 0);
    cudaStreamWaitEvent(s2, ev0, 0);
    cudaStreamWaitEvent(s3, ev0, 0);

    // ---- main stream: critical path (K chain) ----
    conv_hilo_kernel<<<nBig / 1024, 256>>>(keys, KAhi, KAlo, nBig);
    conv_wt_kernel<<<cw, 256>>>(Wk, WKhi, WKlo);
    gemm_mma_kernel<<<gBig, 256, GEMM_SMEM>>>(KAhi, KAlo, WKhi, WKlo, Kp, nullptr, nullptr, nullptr, M, N, K);

    // ---- s1: Q chain ----
    conv_hilo_kernel<<<nBig / 1024, 256, 0, s1>>>(queries, QAhi, QAlo, nBig);
    conv_wt_kernel<<<cw, 256, 0, s1>>>(Wq, WQhi, WQlo);
    gemm_mma_kernel<<<gBig, 256, GEMM_SMEM, s1>>>(QAhi, QAlo, WQhi, WQlo, nullptr, nullptr, Qhi, Qlo, M, N, K);
    cudaEventRecord(evQ, s1);

    // ---- s2: V chain ----
    conv_hilo_kernel<<<nBig / 1024, 256, 0, s2>>>(values, VAhi, VAlo, nBig);
    conv_wt_kernel<<<cw, 256, 0, s2>>>(Wv, WVhi, WVlo);
    gemm_mma_kernel<<<gBig, 256, GEMM_SMEM, s2>>>(VAhi, VAlo, WVhi, WVlo, nullptr, nullptr, Vhi, Vlo, M, N, K);
    cudaEventRecord(evV, s2);

    // ---- s3: router chain + Wo conversion ----
    conv_hilo_kernel<<<nRtr / 1024, 256, 0, s3>>>(routers, RAhi, RAlo, nRtr);
    conv_wt_kernel<<<cw, 256, 0, s3>>>(Wlq, WLQhi, WLQlo);
    gemm_mma_kernel<<<gRtr, 256, GEMM_SMEM, s3>>>(RAhi, RAlo, WLQhi, WLQlo, RQ, nullptr, nullptr, nullptr, Mr, N, K);
    conv_wt_kernel<<<cw, 256, 0, s3>>>(Wlk, WLKhi, WLKlo);
    gemm_mma_kernel<<<gRtr, 256, GEMM_SMEM, s3>>>(RAhi, RAlo, WLKhi, WLKlo, RK, nullptr, nullptr, nullptr, Mr, N, K);
    wep_kernel<<<NB * NH, 256, 0, s3>>>(RQ, RK, WEP);
    cudaEventRecord(evR, s3);
    conv_wt_kernel<<<cw, 256, 0, s3>>>(Wo, WOhi, WOlo);
    cudaEventRecord(evWo, s3);

    // ---- main: kprime (needs K + WEP) ----
    cudaStreamWaitEvent(0, evR, 0);
    dim3 gKP(NL / 64, NB * NH);
    kprime_kernel<<<gKP, 256>>>(Kp, WEP, KPhi, KPlo);

    // ---- main: attention (needs Q, V, KP) ----
    cudaStreamWaitEvent(0, evQ, 0);
    cudaStreamWaitEvent(0, evV, 0);
    dim3 gAtt(NL / 128, NB * NH);
    attn_mma_kernel<<<gAtt, 256, ATT_SMEM>>>(Qhi, Qlo, KPhi, KPlo, Vhi, Vlo, OThi, OTlo);

    // ---- main: final GEMM with bias ----
    cudaStreamWaitEvent(0, evWo, 0);
    gemm_mma_kernel<<<gBig, 256, GEMM_SMEM>>>(OThi, OTlo, WOhi, WOlo, out, bo, nullptr, nullptr, M, N, K);
}